// round 9
// baseline (speedup 1.0000x reference)
#include <cuda_runtime.h>
#include <math.h>
#include <stdint.h>

#define BB 16384

// ---------------- device scratch (static, no allocation) ----------------
__device__ float g_PR[(size_t)BB * 1280];       // per-row: P(1024) | R(256)
__device__ float g_S[(size_t)BB * 256];         // pre-LN scratch
__device__ float g_Z1[(size_t)BB * 256];
// tf32 hi/lo planes
__device__ uint32_t g_Xh[(size_t)BB * 128], g_Xl[(size_t)BB * 128];
__device__ uint32_t g_WcatH[128 * 1280], g_WcatL[128 * 1280];
__device__ uint32_t g_WvH[256 * 256], g_WvL[256 * 256];
__device__ uint32_t g_W1H[256 * 256], g_W1L[256 * 256];
__device__ uint32_t g_W2H[256 * 256], g_W2L[256 * 256];
__device__ uint32_t g_Uh[(size_t)BB * 1024], g_Ul[(size_t)BB * 1024];
__device__ uint32_t g_Z1h[(size_t)BB * 256], g_Z1l[(size_t)BB * 256];
__device__ uint32_t g_H1h[(size_t)BB * 256], g_H1l[(size_t)BB * 256];

// ---------------- helpers ----------------
__device__ __forceinline__ float wsum(float v) {
#pragma unroll
  for (int o = 16; o; o >>= 1) v += __shfl_xor_sync(0xffffffffu, v, o);
  return v;
}
__device__ __forceinline__ float wmax(float v) {
#pragma unroll
  for (int o = 16; o; o >>= 1) v = fmaxf(v, __shfl_xor_sync(0xffffffffu, v, o));
  return v;
}

#define FMA2(d, a, b) \
  asm("fma.rn.f32x2 %0, %1, %2, %0;" : "+l"(d) : "l"(a), "l"(b))
__device__ __forceinline__ unsigned long long dup2(float x) {
  unsigned long long r;
  asm("mov.b64 %0, {%1, %1};" : "=l"(r) : "f"(x));
  return r;
}
__device__ __forceinline__ float2 unpk(unsigned long long p) {
  float2 r;
  asm("mov.b64 {%0, %1}, %2;" : "=f"(r.x), "=f"(r.y) : "l"(p));
  return r;
}

__device__ __forceinline__ uint32_t f2tf32(float f) {
  uint32_t u;
  asm("cvt.rna.tf32.f32 %0, %1;" : "=r"(u) : "f"(f));
  return u;
}
__device__ __forceinline__ void split_tf32(float x, uint32_t& h, uint32_t& l) {
  h = f2tf32(x);
  l = f2tf32(x - __uint_as_float(h));
}
__device__ __forceinline__ void mma_tf32(float* d, const uint32_t* a, const uint32_t* b) {
  asm volatile(
      "mma.sync.aligned.m16n8k8.row.col.f32.tf32.tf32.f32 "
      "{%0,%1,%2,%3}, {%4,%5,%6,%7}, {%8,%9}, {%0,%1,%2,%3};"
      : "+f"(d[0]), "+f"(d[1]), "+f"(d[2]), "+f"(d[3])
      : "r"(a[0]), "r"(a[1]), "r"(a[2]), "r"(a[3]), "r"(b[0]), "r"(b[1]));
}

// bank swizzle for kv rows (attn)
__device__ __forceinline__ int SW(int d) {
  return (d & ~31) | ((d & 31) ^ (((d >> 5) & 3) << 2));
}

// FMA-pipe sincos. Valid for |z| <~ 1e4.
__device__ __forceinline__ void fast_sincos(float z, float& s, float& c) {
  float t = rintf(z * 0.63661977236758134f);
  int qi = (int)t;
  float r = fmaf(t, -1.5703125f, z);
  r = fmaf(t, -4.83751296997070312e-4f, r);
  r = fmaf(t, -7.54978995489188e-8f, r);
  float r2 = r * r;
  float sp = fmaf(r2, -1.9515296e-4f, 8.3321608e-3f);
  sp = fmaf(r2, sp, -1.6666654611e-1f);
  float sinr = fmaf(r * r2, sp, r);
  float cp = fmaf(r2, -1.388731625493765e-3f, 4.166664568298827e-2f);
  cp = fmaf(r2, cp, -0.5f);
  float cosr = fmaf(r2, cp, 1.0f);
  int qq = qi & 3;
  float ss = (qq & 1) ? cosr : sinr;
  float cc = (qq & 1) ? sinr : cosr;
  s = (qq & 2) ? -ss : ss;
  c = ((qq + 1) & 2) ? -cc : cc;
}

// ---------------- cvt: fp32 -> tf32 hi/lo planes ----------------
__global__ void __launch_bounds__(256) cvt_pl(const float* __restrict__ src,
                                              uint32_t* __restrict__ h,
                                              uint32_t* __restrict__ l, int n4) {
  int i = blockIdx.x * 256 + threadIdx.x;
  if (i < n4) {
    float4 v = *(const float4*)&src[i * 4];
    uint4 hv, lv;
    split_tf32(v.x, hv.x, lv.x);
    split_tf32(v.y, hv.y, lv.y);
    split_tf32(v.z, hv.z, lv.z);
    split_tf32(v.w, hv.w, lv.w);
    *(uint4*)&h[i * 4] = hv;
    *(uint4*)&l[i * 4] = lv;
  }
}

// ---------------- K0: MQK planes ----------------
__global__ void __launch_bounds__(256) mqk_kernel(const float* __restrict__ Wq,
                                                  const float* __restrict__ Wk) {
  __shared__ float sWq[16 * 68];
  __shared__ float sWk[128 * 68];
  int h = blockIdx.x, is = blockIdx.y;
  int tid = threadIdx.x;
  {
    int il = tid >> 4, d4 = tid & 15;
    *(float4*)&sWq[il * 68 + d4 * 4] =
        *(const float4*)&Wq[(size_t)(is * 16 + il) * 256 + h * 64 + d4 * 4];
  }
  for (int jc = 0; jc < 2; jc++) {
    __syncthreads();
#pragma unroll
    for (int it = 0; it < 8; it++) {
      int f = tid + it * 256;
      int j = f >> 4, d4 = f & 15;
      *(float4*)&sWk[j * 68 + d4 * 4] =
          *(const float4*)&Wk[(size_t)(jc * 128 + j) * 256 + h * 64 + d4 * 4];
    }
    __syncthreads();
    int j = tid & 127, ih = tid >> 7;
#pragma unroll 1
    for (int il = ih * 8; il < ih * 8 + 8; il++) {
      float acc = 0.f;
#pragma unroll
      for (int d = 0; d < 64; d++) acc = fmaf(sWq[il * 68 + d], sWk[j * 68 + d], acc);
      uint32_t hh, ll;
      split_tf32(acc, hh, ll);
      size_t idx = (size_t)(is * 16 + il) * 1280 + h * 256 + jc * 128 + j;
      g_WcatH[idx] = hh;
      g_WcatL[idx] = ll;
    }
  }
}

__global__ void copy_wres_kernel(const float* __restrict__ Wres) {
  int i = blockIdx.x, tid = threadIdx.x;
  uint32_t hh, ll;
  split_tf32(Wres[(size_t)i * 256 + tid], hh, ll);
  size_t idx = (size_t)i * 1280 + 1024 + tid;
  g_WcatH[idx] = hh;
  g_WcatL[idx] = ll;
}

// ---------------- tf32 3-pass tensor GEMM ----------------
// Block 64 x (NF*16), 128 threads (warps 2x2), warp tile 32 x (NF*8).
// A planes row-major [M][lda] (+ hz*zA col offset), B planes [K][ldb] (+ hz*zB).
// EPI 0: C fp32. EPI 1: relu(x+bias) -> Ch/Cl planes.
template <int NF, int EPI>
__global__ void __launch_bounds__(128) gemm_tc(
    const uint32_t* __restrict__ Ah, const uint32_t* __restrict__ Al, int lda, int zA,
    const uint32_t* __restrict__ Bh, const uint32_t* __restrict__ Bl, int ldb, int zB,
    float* __restrict__ C, uint32_t* __restrict__ Ch, uint32_t* __restrict__ Cl,
    int ldc, int zC, int K, const float* __restrict__ bias) {
  constexpr int BN = NF * 16;
  constexpr int BPAD = BN + 8;
  constexpr int C4N = BN / 4;
  extern __shared__ uint32_t sm[];
  uint32_t* sAh = sm;                    // 64*36
  uint32_t* sAl = sAh + 64 * 36;
  uint32_t* sBh = sAl + 64 * 36;         // 32*BPAD
  uint32_t* sBl = sBh + 32 * BPAD;

  int tid = threadIdx.x, lane = tid & 31, wid = tid >> 5;
  int wm = wid >> 1, wn = wid & 1;
  int g = lane >> 2, tg = lane & 3;
  int m0 = blockIdx.y * 64, nb0 = blockIdx.x * BN;
  int hz = blockIdx.z;
  const uint32_t* pAh = Ah + hz * zA;
  const uint32_t* pAl = Al + hz * zA;
  const uint32_t* pBh = Bh + hz * zB;
  const uint32_t* pBl = Bl + hz * zB;

  float acc[2][NF][4];
#pragma unroll
  for (int mf = 0; mf < 2; mf++)
#pragma unroll
    for (int nf = 0; nf < NF; nf++)
#pragma unroll
      for (int q = 0; q < 4; q++) acc[mf][nf][q] = 0.f;

  int kt_n = K >> 5;
  for (int kt = 0; kt < kt_n; kt++) {
    __syncthreads();
    // A tile 64x32 (both planes)
#pragma unroll
    for (int it = 0; it < 4; it++) {
      int f = tid + it * 128, r = f >> 3, kq = f & 7;
      size_t src = (size_t)(m0 + r) * lda + kt * 32 + kq * 4;
      *(uint4*)&sAh[r * 36 + kq * 4] = *(const uint4*)&pAh[src];
      *(uint4*)&sAl[r * 36 + kq * 4] = *(const uint4*)&pAl[src];
    }
    // B tile 32xBN (both planes): 32*C4N uint4 per plane, 128 threads -> NF iters
#pragma unroll
    for (int it = 0; it < NF; it++) {
      int f = tid + it * 128;
      int kk = f / C4N, c4 = f % C4N;
      size_t src = (size_t)(kt * 32 + kk) * ldb + nb0 + c4 * 4;
      *(uint4*)&sBh[kk * BPAD + c4 * 4] = *(const uint4*)&pBh[src];
      *(uint4*)&sBl[kk * BPAD + c4 * 4] = *(const uint4*)&pBl[src];
    }
    __syncthreads();
#pragma unroll
    for (int kb = 0; kb < 4; kb++) {
      uint32_t AhF[2][4], AlF[2][4], BhF[NF][2], BlF[NF][2];
#pragma unroll
      for (int mf = 0; mf < 2; mf++) {
        int base = (wm * 32 + mf * 16 + g) * 36 + kb * 8 + tg;
        AhF[mf][0] = sAh[base];
        AhF[mf][1] = sAh[base + 288];
        AhF[mf][2] = sAh[base + 4];
        AhF[mf][3] = sAh[base + 292];
        AlF[mf][0] = sAl[base];
        AlF[mf][1] = sAl[base + 288];
        AlF[mf][2] = sAl[base + 4];
        AlF[mf][3] = sAl[base + 292];
      }
#pragma unroll
      for (int nf = 0; nf < NF; nf++) {
        int bidx = (kb * 8 + tg) * BPAD + wn * NF * 8 + nf * 8 + g;
        BhF[nf][0] = sBh[bidx];
        BhF[nf][1] = sBh[bidx + 4 * BPAD];
        BlF[nf][0] = sBl[bidx];
        BlF[nf][1] = sBl[bidx + 4 * BPAD];
      }
#pragma unroll
      for (int mf = 0; mf < 2; mf++)
#pragma unroll
        for (int nf = 0; nf < NF; nf++) {
          mma_tf32(acc[mf][nf], AhF[mf], BhF[nf]);
          mma_tf32(acc[mf][nf], AhF[mf], BlF[nf]);
          mma_tf32(acc[mf][nf], AlF[mf], BhF[nf]);
        }
    }
  }
  // ---- epilogue ----
#pragma unroll
  for (int mf = 0; mf < 2; mf++) {
    int row0 = m0 + wm * 32 + mf * 16 + g;
#pragma unroll
    for (int nf = 0; nf < NF; nf++) {
      int col = nb0 + hz * zC + wn * NF * 8 + nf * 8 + tg * 2;
      if (EPI == 0) {
        float2 p0 = {acc[mf][nf][0], acc[mf][nf][1]};
        float2 p1 = {acc[mf][nf][2], acc[mf][nf][3]};
        *(float2*)&C[(size_t)row0 * ldc + col] = p0;
        *(float2*)&C[(size_t)(row0 + 8) * ldc + col] = p1;
      } else {
        float b0 = bias[col], b1 = bias[col + 1];
        float v0 = fmaxf(acc[mf][nf][0] + b0, 0.f);
        float v1 = fmaxf(acc[mf][nf][1] + b1, 0.f);
        float v2 = fmaxf(acc[mf][nf][2] + b0, 0.f);
        float v3 = fmaxf(acc[mf][nf][3] + b1, 0.f);
        uint2 h0, l0, h1, l1;
        split_tf32(v0, h0.x, l0.x);
        split_tf32(v1, h0.y, l0.y);
        split_tf32(v2, h1.x, l1.x);
        split_tf32(v3, h1.y, l1.y);
        *(uint2*)&Ch[(size_t)row0 * ldc + col] = h0;
        *(uint2*)&Cl[(size_t)row0 * ldc + col] = l0;
        *(uint2*)&Ch[(size_t)(row0 + 8) * ldc + col] = h1;
        *(uint2*)&Cl[(size_t)(row0 + 8) * ldc + col] = l1;
      }
    }
  }
}

// ---------------- K2: attention -> u planes ----------------
__global__ void __launch_bounds__(256) attn_u_kernel(
    const float* __restrict__ x_ctx, const float* __restrict__ t_ctx,
    const float* __restrict__ freq, const float* __restrict__ phase) {
  __shared__ float kv[32 * 260];
  __shared__ float p2[4 * 8 * 36];
  __shared__ float slog[128];
  __shared__ __align__(16) float sw[128];
  __shared__ float sfr[64], sph[64];
  int b = blockIdx.x, tid = threadIdx.x;
  int l = tid >> 3, sub = tid & 7;

  if (tid < 64) {
    sfr[tid] = freq[tid];
    sph[tid] = phase[tid];
  }
  {
    int h = tid >> 6, r = tid & 63, s2 = r >> 3, c = r & 7;
    int idx4;
    if (c < 4) idx4 = h * 64 + s2 * 4 + c;
    else if (c < 6) idx4 = h * 64 + 32 + s2 * 2 + (c - 4);
    else idx4 = h * 64 + 48 + s2 * 2 + (c - 6);
    float4 v = *(const float4*)&g_PR[(size_t)b * 1280 + (size_t)idx4 * 4];
    *(float4*)&p2[(h * 8 + s2) * 36 + c * 4] = v;
  }
  __syncthreads();

  float acc[4] = {0.f, 0.f, 0.f, 0.f};
  const float* xsrc = x_ctx + ((size_t)b * 32 + l) * 128 + sub * 16;
  float* kvrow = kv + l * 260;

#pragma unroll
  for (int c = 0; c < 4; c++) {
    float4 v = *(const float4*)&xsrc[c * 4];
    *(float4*)&kvrow[SW(sub * 16 + c * 4)] = v;
#pragma unroll
    for (int h = 0; h < 4; h++) {
      float4 p = *(const float4*)&p2[(h * 8 + sub) * 36 + c * 4];
      acc[h] = fmaf(v.x, p.x, acc[h]);
      acc[h] = fmaf(v.y, p.y, acc[h]);
      acc[h] = fmaf(v.z, p.z, acc[h]);
      acc[h] = fmaf(v.w, p.w, acc[h]);
    }
  }
  {
    float t = t_ctx[(size_t)b * 32 + l];
    float lt = log1pf(fmaxf(t, 0.f));
#pragma unroll
    for (int g = 0; g < 2; g++) {
      float4 sv, cv;
      float ss, cc;
      int k0 = sub * 8 + g * 4;
      float z0 = fmaf(lt, sfr[k0 + 0], sph[k0 + 0]);
      float z1 = fmaf(lt, sfr[k0 + 1], sph[k0 + 1]);
      float z2 = fmaf(lt, sfr[k0 + 2], sph[k0 + 2]);
      float z3 = fmaf(lt, sfr[k0 + 3], sph[k0 + 3]);
      fast_sincos(z0, ss, cc); sv.x = ss; cv.x = cc;
      fast_sincos(z1, ss, cc); sv.y = ss; cv.y = cc;
      fast_sincos(z2, ss, cc); sv.z = ss; cv.z = cc;
      fast_sincos(z3, ss, cc); sv.w = ss; cv.w = cc;
      *(float4*)&kvrow[SW(128 + sub * 8 + g * 4)] = sv;
      *(float4*)&kvrow[SW(192 + sub * 8 + g * 4)] = cv;
#pragma unroll
      for (int h = 0; h < 4; h++) {
        float4 ps = *(const float4*)&p2[(h * 8 + sub) * 36 + (4 + g) * 4];
        float4 pc = *(const float4*)&p2[(h * 8 + sub) * 36 + (6 + g) * 4];
        acc[h] = fmaf(sv.x, ps.x, acc[h]);
        acc[h] = fmaf(sv.y, ps.y, acc[h]);
        acc[h] = fmaf(sv.z, ps.z, acc[h]);
        acc[h] = fmaf(sv.w, ps.w, acc[h]);
        acc[h] = fmaf(cv.x, pc.x, acc[h]);
        acc[h] = fmaf(cv.y, pc.y, acc[h]);
        acc[h] = fmaf(cv.z, pc.z, acc[h]);
        acc[h] = fmaf(cv.w, pc.w, acc[h]);
      }
    }
  }
#pragma unroll
  for (int h = 0; h < 4; h++) {
#pragma unroll
    for (int o = 4; o; o >>= 1) acc[h] += __shfl_xor_sync(0xffffffffu, acc[h], o);
  }
  if (sub < 4) slog[sub * 32 + l] = acc[sub] * 0.125f;
  __syncthreads();
  if (tid < 128) {
    int h = tid >> 5, ll = tid & 31;
    float v = slog[tid];
    float m = wmax(v);
    float e = __expf(v - m);
    float s = wsum(e);
    sw[ll * 4 + h] = e / s;
  }
  __syncthreads();
  {
    int swt = SW(tid);
    unsigned long long a01 = 0ull, a23 = 0ull;
#pragma unroll
    for (int ll = 0; ll < 32; ll++) {
      ulonglong2 w2 = *(const ulonglong2*)&sw[ll * 4];
      unsigned long long vd = dup2(kv[ll * 260 + swt]);
      FMA2(a01, vd, w2.x);
      FMA2(a23, vd, w2.y);
    }
    float2 u01 = unpk(a01);
    float2 u23 = unpk(a23);
    size_t o = (size_t)b * 1024 + tid;
    uint32_t hh, ll2;
    split_tf32(u01.x, hh, ll2); g_Uh[o] = hh; g_Ul[o] = ll2;
    split_tf32(u01.y, hh, ll2); g_Uh[o + 256] = hh; g_Ul[o + 256] = ll2;
    split_tf32(u23.x, hh, ll2); g_Uh[o + 512] = hh; g_Ul[o + 512] = ll2;
    split_tf32(u23.y, hh, ll2); g_Uh[o + 768] = hh; g_Ul[o + 768] = ll2;
  }
}

// ---------------- LN: out = LN(S + resid + bias)*gamma + beta (+ planes) --------
template <bool EMIT>
__global__ void __launch_bounds__(256) ln_kernel(
    const float* __restrict__ S, const float* __restrict__ resid, int ldres,
    const float* __restrict__ bias, const float* __restrict__ gamma,
    const float* __restrict__ beta, float* __restrict__ out,
    uint32_t* __restrict__ outH, uint32_t* __restrict__ outL) {
  int row = blockIdx.x * 8 + (threadIdx.x >> 5);
  int lane = threadIdx.x & 31;
  int c0 = lane * 4, c1 = 128 + lane * 4;
  float4 a0 = *(const float4*)&S[(size_t)row * 256 + c0];
  float4 a1 = *(const float4*)&S[(size_t)row * 256 + c1];
  float4 r0 = *(const float4*)&resid[(size_t)row * ldres + c0];
  float4 r1 = *(const float4*)&resid[(size_t)row * ldres + c1];
  float4 b0 = *(const float4*)&bias[c0];
  float4 b1 = *(const float4*)&bias[c1];
  float v[8];
  v[0] = a0.x + r0.x + b0.x;
  v[1] = a0.y + r0.y + b0.y;
  v[2] = a0.z + r0.z + b0.z;
  v[3] = a0.w + r0.w + b0.w;
  v[4] = a1.x + r1.x + b1.x;
  v[5] = a1.y + r1.y + b1.y;
  v[6] = a1.z + r1.z + b1.z;
  v[7] = a1.w + r1.w + b1.w;
  float s = 0.f;
#pragma unroll
  for (int j = 0; j < 8; j++) s += v[j];
  s = wsum(s);
  float mean = s * (1.f / 256.f);
  float q = 0.f;
#pragma unroll
  for (int j = 0; j < 8; j++) {
    float d = v[j] - mean;
    q += d * d;
  }
  q = wsum(q);
  float rstd = rsqrtf(q * (1.f / 256.f) + 1e-5f);
  float4 g0 = *(const float4*)&gamma[c0];
  float4 g1 = *(const float4*)&gamma[c1];
  float4 e0 = *(const float4*)&beta[c0];
  float4 e1 = *(const float4*)&beta[c1];
  float o[8];
  o[0] = (v[0] - mean) * rstd * g0.x + e0.x;
  o[1] = (v[1] - mean) * rstd * g0.y + e0.y;
  o[2] = (v[2] - mean) * rstd * g0.z + e0.z;
  o[3] = (v[3] - mean) * rstd * g0.w + e0.w;
  o[4] = (v[4] - mean) * rstd * g1.x + e1.x;
  o[5] = (v[5] - mean) * rstd * g1.y + e1.y;
  o[6] = (v[6] - mean) * rstd * g1.z + e1.z;
  o[7] = (v[7] - mean) * rstd * g1.w + e1.w;
  float4 of0 = {o[0], o[1], o[2], o[3]};
  float4 of1 = {o[4], o[5], o[6], o[7]};
  *(float4*)&out[(size_t)row * 256 + c0] = of0;
  *(float4*)&out[(size_t)row * 256 + c1] = of1;
  if (EMIT) {
    uint4 h0, l0, h1, l1;
    split_tf32(o[0], h0.x, l0.x);
    split_tf32(o[1], h0.y, l0.y);
    split_tf32(o[2], h0.z, l0.z);
    split_tf32(o[3], h0.w, l0.w);
    split_tf32(o[4], h1.x, l1.x);
    split_tf32(o[5], h1.y, l1.y);
    split_tf32(o[6], h1.z, l1.z);
    split_tf32(o[7], h1.w, l1.w);
    *(uint4*)&outH[(size_t)row * 256 + c0] = h0;
    *(uint4*)&outL[(size_t)row * 256 + c0] = l0;
    *(uint4*)&outH[(size_t)row * 256 + c1] = h1;
    *(uint4*)&outL[(size_t)row * 256 + c1] = l1;
  }
}

// ---------------- launch ----------------
extern "C" void kernel_launch(void* const* d_in, const int* in_sizes, int n_in,
                              void* d_out, int out_size) {
  const float* x_u   = (const float*)d_in[0];
  const float* x_ctx = (const float*)d_in[1];
  const float* t_ctx = (const float*)d_in[2];
  const float* freq  = (const float*)d_in[3];
  const float* phase = (const float*)d_in[4];
  const float* Wq    = (const float*)d_in[5];
  const float* Wk    = (const float*)d_in[6];
  const float* Wv    = (const float*)d_in[7];
  const float* Wres  = (const float*)d_in[8];
  const float* bres  = (const float*)d_in[9];
  const float* W1    = (const float*)d_in[10];
  const float* b1    = (const float*)d_in[11];
  const float* W2    = (const float*)d_in[12];
  const float* b2    = (const float*)d_in[13];
  const float* g1    = (const float*)d_in[14];
  const float* be1   = (const float*)d_in[15];
  const float* g2    = (const float*)d_in[16];
  const float* be2   = (const float*)d_in[17];
  float* out = (float*)d_out;

  float *pPR, *pS, *pZ1;
  uint32_t *pXh, *pXl, *pWcatH, *pWcatL, *pWvH, *pWvL, *pW1H, *pW1L, *pW2H, *pW2L;
  uint32_t *pUh, *pUl, *pZ1h, *pZ1l, *pH1h, *pH1l;
  cudaGetSymbolAddress((void**)&pPR, g_PR);
  cudaGetSymbolAddress((void**)&pS, g_S);
  cudaGetSymbolAddress((void**)&pZ1, g_Z1);
  cudaGetSymbolAddress((void**)&pXh, g_Xh);
  cudaGetSymbolAddress((void**)&pXl, g_Xl);
  cudaGetSymbolAddress((void**)&pWcatH, g_WcatH);
  cudaGetSymbolAddress((void**)&pWcatL, g_WcatL);
  cudaGetSymbolAddress((void**)&pWvH, g_WvH);
  cudaGetSymbolAddress((void**)&pWvL, g_WvL);
  cudaGetSymbolAddress((void**)&pW1H, g_W1H);
  cudaGetSymbolAddress((void**)&pW1L, g_W1L);
  cudaGetSymbolAddress((void**)&pW2H, g_W2H);
  cudaGetSymbolAddress((void**)&pW2L, g_W2L);
  cudaGetSymbolAddress((void**)&pUh, g_Uh);
  cudaGetSymbolAddress((void**)&pUl, g_Ul);
  cudaGetSymbolAddress((void**)&pZ1h, g_Z1h);
  cudaGetSymbolAddress((void**)&pZ1l, g_Z1l);
  cudaGetSymbolAddress((void**)&pH1h, g_H1h);
  cudaGetSymbolAddress((void**)&pH1l, g_H1l);

  int smem8 = (2 * 64 * 36 + 2 * 32 * 136) * 4;  // 53,248 B
  int smem4 = (2 * 64 * 36 + 2 * 32 * 72) * 4;   // 36,864 B
  cudaFuncSetAttribute(gemm_tc<8, 0>, cudaFuncAttributeMaxDynamicSharedMemorySize, smem8);
  cudaFuncSetAttribute(gemm_tc<8, 1>, cudaFuncAttributeMaxDynamicSharedMemorySize, smem8);
  cudaFuncSetAttribute(gemm_tc<4, 0>, cudaFuncAttributeMaxDynamicSharedMemorySize, smem4);

  // prep: convert operands to tf32 planes
  cvt_pl<<<(BB * 128 / 4 + 255) / 256, 256>>>(x_u, pXh, pXl, BB * 128 / 4);
  cvt_pl<<<64, 256>>>(Wv, pWvH, pWvL, 256 * 256 / 4);
  cvt_pl<<<64, 256>>>(W1, pW1H, pW1L, 256 * 256 / 4);
  cvt_pl<<<64, 256>>>(W2, pW2H, pW2L, 256 * 256 / 4);
  mqk_kernel<<<dim3(4, 8), 256>>>(Wq, Wk);
  copy_wres_kernel<<<128, 256>>>(Wres);

  // K1: P|R = x_u @ Wcat
  gemm_tc<8, 0><<<dim3(10, 256, 1), 128, smem8>>>(
      pXh, pXl, 128, 0, pWcatH, pWcatL, 1280, 0,
      pPR, nullptr, nullptr, 1280, 0, 128, nullptr);

  // K2: attention -> u planes
  attn_u_kernel<<<BB, 256>>>(x_ctx, t_ctx, freq, phase);

  // K3: S = u_h @ Wv_h (per head via z); z1 = LN(S + R + bres)
  gemm_tc<4, 0><<<dim3(1, 256, 4), 128, smem4>>>(
      pUh, pUl, 1024, 256, pWvH, pWvL, 256, 64,
      pS, nullptr, nullptr, 256, 64, 256, nullptr);
  ln_kernel<true><<<BB / 8, 256>>>(pS, pPR + 1024, 1280, bres, g1, be1, pZ1, pZ1h, pZ1l);

  // K4: h1 = relu(z1 @ W1 + b1) -> planes
  gemm_tc<8, 1><<<dim3(2, 256, 1), 128, smem8>>>(
      pZ1h, pZ1l, 256, 0, pW1H, pW1L, 256, 0,
      nullptr, pH1h, pH1l, 256, 0, 256, b1);

  // K5: S = h1 @ W2 ; out = LN(S + z1 + b2)
  gemm_tc<8, 0><<<dim3(2, 256, 1), 128, smem8>>>(
      pH1h, pH1l, 256, 0, pW2H, pW2L, 256, 0,
      pS, nullptr, nullptr, 256, 0, 256, nullptr);
  ln_kernel<false><<<BB / 8, 256>>>(pS, pZ1, 256, b2, g2, be2, out, nullptr, nullptr);
}

// round 10
// speedup vs baseline: 1.0026x; 1.0026x over previous
#include <cuda_runtime.h>
#include <math.h>
#include <stdint.h>

#define BB 16384

// ---------------- device scratch (static, no allocation) ----------------
__device__ float g_PR[(size_t)BB * 1280];       // per-row: P(1024) | R(256)
__device__ float g_S[(size_t)BB * 256];         // pre-LN scratch
__device__ float g_Z1[(size_t)BB * 256];
// tf32 hi/lo planes
__device__ uint32_t g_Xh[(size_t)BB * 128], g_Xl[(size_t)BB * 128];
__device__ uint32_t g_WcatH[128 * 1280], g_WcatL[128 * 1280];
__device__ uint32_t g_WvH[256 * 256], g_WvL[256 * 256];
__device__ uint32_t g_W1H[256 * 256], g_W1L[256 * 256];
__device__ uint32_t g_W2H[256 * 256], g_W2L[256 * 256];
__device__ uint32_t g_Uh[(size_t)BB * 1024], g_Ul[(size_t)BB * 1024];
__device__ uint32_t g_Z1h[(size_t)BB * 256], g_Z1l[(size_t)BB * 256];
__device__ uint32_t g_H1h[(size_t)BB * 256], g_H1l[(size_t)BB * 256];

// ---------------- helpers ----------------
__device__ __forceinline__ float wsum(float v) {
#pragma unroll
  for (int o = 16; o; o >>= 1) v += __shfl_xor_sync(0xffffffffu, v, o);
  return v;
}
__device__ __forceinline__ float wmax(float v) {
#pragma unroll
  for (int o = 16; o; o >>= 1) v = fmaxf(v, __shfl_xor_sync(0xffffffffu, v, o));
  return v;
}

#define FMA2(d, a, b) \
  asm("fma.rn.f32x2 %0, %1, %2, %0;" : "+l"(d) : "l"(a), "l"(b))
__device__ __forceinline__ unsigned long long dup2(float x) {
  unsigned long long r;
  asm("mov.b64 %0, {%1, %1};" : "=l"(r) : "f"(x));
  return r;
}
__device__ __forceinline__ float2 unpk(unsigned long long p) {
  float2 r;
  asm("mov.b64 {%0, %1}, %2;" : "=f"(r.x), "=f"(r.y) : "l"(p));
  return r;
}

__device__ __forceinline__ uint32_t f2tf32(float f) {
  uint32_t u;
  asm("cvt.rna.tf32.f32 %0, %1;" : "=r"(u) : "f"(f));
  return u;
}
__device__ __forceinline__ void split_tf32(float x, uint32_t& h, uint32_t& l) {
  h = f2tf32(x);
  l = f2tf32(x - __uint_as_float(h));
}
__device__ __forceinline__ void mma_tf32(float* d, const uint32_t* a, const uint32_t* b) {
  asm volatile(
      "mma.sync.aligned.m16n8k8.row.col.f32.tf32.tf32.f32 "
      "{%0,%1,%2,%3}, {%4,%5,%6,%7}, {%8,%9}, {%0,%1,%2,%3};"
      : "+f"(d[0]), "+f"(d[1]), "+f"(d[2]), "+f"(d[3])
      : "r"(a[0]), "r"(a[1]), "r"(a[2]), "r"(a[3]), "r"(b[0]), "r"(b[1]));
}

// bank swizzle for kv rows (attn)
__device__ __forceinline__ int SW(int d) {
  return (d & ~31) | ((d & 31) ^ (((d >> 5) & 3) << 2));
}

// FMA-pipe sincos. Valid for |z| <~ 1e4.
__device__ __forceinline__ void fast_sincos(float z, float& s, float& c) {
  float t = rintf(z * 0.63661977236758134f);
  int qi = (int)t;
  float r = fmaf(t, -1.5703125f, z);
  r = fmaf(t, -4.83751296997070312e-4f, r);
  r = fmaf(t, -7.54978995489188e-8f, r);
  float r2 = r * r;
  float sp = fmaf(r2, -1.9515296e-4f, 8.3321608e-3f);
  sp = fmaf(r2, sp, -1.6666654611e-1f);
  float sinr = fmaf(r * r2, sp, r);
  float cp = fmaf(r2, -1.388731625493765e-3f, 4.166664568298827e-2f);
  cp = fmaf(r2, cp, -0.5f);
  float cosr = fmaf(r2, cp, 1.0f);
  int qq = qi & 3;
  float ss = (qq & 1) ? cosr : sinr;
  float cc = (qq & 1) ? sinr : cosr;
  s = (qq & 2) ? -ss : ss;
  c = ((qq + 1) & 2) ? -cc : cc;
}

// ---------------- cvt: fp32 -> tf32 hi/lo planes ----------------
__global__ void __launch_bounds__(256) cvt_pl(const float* __restrict__ src,
                                              uint32_t* __restrict__ h,
                                              uint32_t* __restrict__ l, int n4) {
  int i = blockIdx.x * 256 + threadIdx.x;
  if (i < n4) {
    float4 v = *(const float4*)&src[i * 4];
    uint4 hv, lv;
    split_tf32(v.x, hv.x, lv.x);
    split_tf32(v.y, hv.y, lv.y);
    split_tf32(v.z, hv.z, lv.z);
    split_tf32(v.w, hv.w, lv.w);
    *(uint4*)&h[i * 4] = hv;
    *(uint4*)&l[i * 4] = lv;
  }
}

// ---------------- K0: MQK planes ----------------
__global__ void __launch_bounds__(256) mqk_kernel(const float* __restrict__ Wq,
                                                  const float* __restrict__ Wk) {
  __shared__ float sWq[16 * 68];
  __shared__ float sWk[128 * 68];
  int h = blockIdx.x, is = blockIdx.y;
  int tid = threadIdx.x;
  {
    int il = tid >> 4, d4 = tid & 15;
    *(float4*)&sWq[il * 68 + d4 * 4] =
        *(const float4*)&Wq[(size_t)(is * 16 + il) * 256 + h * 64 + d4 * 4];
  }
  for (int jc = 0; jc < 2; jc++) {
    __syncthreads();
#pragma unroll
    for (int it = 0; it < 8; it++) {
      int f = tid + it * 256;
      int j = f >> 4, d4 = f & 15;
      *(float4*)&sWk[j * 68 + d4 * 4] =
          *(const float4*)&Wk[(size_t)(jc * 128 + j) * 256 + h * 64 + d4 * 4];
    }
    __syncthreads();
    int j = tid & 127, ih = tid >> 7;
#pragma unroll 1
    for (int il = ih * 8; il < ih * 8 + 8; il++) {
      float acc = 0.f;
#pragma unroll
      for (int d = 0; d < 64; d++) acc = fmaf(sWq[il * 68 + d], sWk[j * 68 + d], acc);
      uint32_t hh, ll;
      split_tf32(acc, hh, ll);
      size_t idx = (size_t)(is * 16 + il) * 1280 + h * 256 + jc * 128 + j;
      g_WcatH[idx] = hh;
      g_WcatL[idx] = ll;
    }
  }
}

__global__ void copy_wres_kernel(const float* __restrict__ Wres) {
  int i = blockIdx.x, tid = threadIdx.x;
  uint32_t hh, ll;
  split_tf32(Wres[(size_t)i * 256 + tid], hh, ll);
  size_t idx = (size_t)i * 1280 + 1024 + tid;
  g_WcatH[idx] = hh;
  g_WcatL[idx] = ll;
}

// ---------------- tf32 3-pass tensor GEMM ----------------
// Block 64 x (NF*16), 128 threads (warps 2x2), warp tile 32 x (NF*8).
// A planes row-major [M][lda] (+ hz*zA col offset), B planes [K][ldb] (+ hz*zB).
// EPI 0: C fp32. EPI 1: relu(x+bias) -> Ch/Cl planes.
template <int NF, int EPI>
__global__ void __launch_bounds__(128) gemm_tc(
    const uint32_t* __restrict__ Ah, const uint32_t* __restrict__ Al, int lda, int zA,
    const uint32_t* __restrict__ Bh, const uint32_t* __restrict__ Bl, int ldb, int zB,
    float* __restrict__ C, uint32_t* __restrict__ Ch, uint32_t* __restrict__ Cl,
    int ldc, int zC, int K, const float* __restrict__ bias) {
  constexpr int BN = NF * 16;
  constexpr int BPAD = BN + 8;
  constexpr int C4N = BN / 4;
  extern __shared__ uint32_t sm[];
  uint32_t* sAh = sm;                    // 64*36
  uint32_t* sAl = sAh + 64 * 36;
  uint32_t* sBh = sAl + 64 * 36;         // 32*BPAD
  uint32_t* sBl = sBh + 32 * BPAD;

  int tid = threadIdx.x, lane = tid & 31, wid = tid >> 5;
  int wm = wid >> 1, wn = wid & 1;
  int g = lane >> 2, tg = lane & 3;
  int m0 = blockIdx.y * 64, nb0 = blockIdx.x * BN;
  int hz = blockIdx.z;
  const uint32_t* pAh = Ah + hz * zA;
  const uint32_t* pAl = Al + hz * zA;
  const uint32_t* pBh = Bh + hz * zB;
  const uint32_t* pBl = Bl + hz * zB;

  float acc[2][NF][4];
#pragma unroll
  for (int mf = 0; mf < 2; mf++)
#pragma unroll
    for (int nf = 0; nf < NF; nf++)
#pragma unroll
      for (int q = 0; q < 4; q++) acc[mf][nf][q] = 0.f;

  int kt_n = K >> 5;
  for (int kt = 0; kt < kt_n; kt++) {
    __syncthreads();
    // A tile 64x32 (both planes)
#pragma unroll
    for (int it = 0; it < 4; it++) {
      int f = tid + it * 128, r = f >> 3, kq = f & 7;
      size_t src = (size_t)(m0 + r) * lda + kt * 32 + kq * 4;
      *(uint4*)&sAh[r * 36 + kq * 4] = *(const uint4*)&pAh[src];
      *(uint4*)&sAl[r * 36 + kq * 4] = *(const uint4*)&pAl[src];
    }
    // B tile 32xBN (both planes): 32*C4N uint4 per plane, 128 threads -> NF iters
#pragma unroll
    for (int it = 0; it < NF; it++) {
      int f = tid + it * 128;
      int kk = f / C4N, c4 = f % C4N;
      size_t src = (size_t)(kt * 32 + kk) * ldb + nb0 + c4 * 4;
      *(uint4*)&sBh[kk * BPAD + c4 * 4] = *(const uint4*)&pBh[src];
      *(uint4*)&sBl[kk * BPAD + c4 * 4] = *(const uint4*)&pBl[src];
    }
    __syncthreads();
#pragma unroll
    for (int kb = 0; kb < 4; kb++) {
      uint32_t AhF[2][4], AlF[2][4], BhF[NF][2], BlF[NF][2];
#pragma unroll
      for (int mf = 0; mf < 2; mf++) {
        int base = (wm * 32 + mf * 16 + g) * 36 + kb * 8 + tg;
        AhF[mf][0] = sAh[base];
        AhF[mf][1] = sAh[base + 288];
        AhF[mf][2] = sAh[base + 4];
        AhF[mf][3] = sAh[base + 292];
        AlF[mf][0] = sAl[base];
        AlF[mf][1] = sAl[base + 288];
        AlF[mf][2] = sAl[base + 4];
        AlF[mf][3] = sAl[base + 292];
      }
#pragma unroll
      for (int nf = 0; nf < NF; nf++) {
        int bidx = (kb * 8 + tg) * BPAD + wn * NF * 8 + nf * 8 + g;
        BhF[nf][0] = sBh[bidx];
        BhF[nf][1] = sBh[bidx + 4 * BPAD];
        BlF[nf][0] = sBl[bidx];
        BlF[nf][1] = sBl[bidx + 4 * BPAD];
      }
#pragma unroll
      for (int mf = 0; mf < 2; mf++)
#pragma unroll
        for (int nf = 0; nf < NF; nf++) {
          mma_tf32(acc[mf][nf], AhF[mf], BhF[nf]);
          mma_tf32(acc[mf][nf], AhF[mf], BlF[nf]);
          mma_tf32(acc[mf][nf], AlF[mf], BhF[nf]);
        }
    }
  }
  // ---- epilogue ----
#pragma unroll
  for (int mf = 0; mf < 2; mf++) {
    int row0 = m0 + wm * 32 + mf * 16 + g;
#pragma unroll
    for (int nf = 0; nf < NF; nf++) {
      int col = nb0 + hz * zC + wn * NF * 8 + nf * 8 + tg * 2;
      if (EPI == 0) {
        float2 p0 = {acc[mf][nf][0], acc[mf][nf][1]};
        float2 p1 = {acc[mf][nf][2], acc[mf][nf][3]};
        *(float2*)&C[(size_t)row0 * ldc + col] = p0;
        *(float2*)&C[(size_t)(row0 + 8) * ldc + col] = p1;
      } else {
        float b0 = bias[col], b1 = bias[col + 1];
        float v0 = fmaxf(acc[mf][nf][0] + b0, 0.f);
        float v1 = fmaxf(acc[mf][nf][1] + b1, 0.f);
        float v2 = fmaxf(acc[mf][nf][2] + b0, 0.f);
        float v3 = fmaxf(acc[mf][nf][3] + b1, 0.f);
        uint2 h0, l0, h1, l1;
        split_tf32(v0, h0.x, l0.x);
        split_tf32(v1, h0.y, l0.y);
        split_tf32(v2, h1.x, l1.x);
        split_tf32(v3, h1.y, l1.y);
        *(uint2*)&Ch[(size_t)row0 * ldc + col] = h0;
        *(uint2*)&Cl[(size_t)row0 * ldc + col] = l0;
        *(uint2*)&Ch[(size_t)(row0 + 8) * ldc + col] = h1;
        *(uint2*)&Cl[(size_t)(row0 + 8) * ldc + col] = l1;
      }
    }
  }
}

// ---------------- K2: attention -> u planes ----------------
__global__ void __launch_bounds__(256) attn_u_kernel(
    const float* __restrict__ x_ctx, const float* __restrict__ t_ctx,
    const float* __restrict__ freq, const float* __restrict__ phase) {
  __shared__ float kv[32 * 260];
  __shared__ float p2[4 * 8 * 36];
  __shared__ float slog[128];
  __shared__ __align__(16) float sw[128];
  __shared__ float sfr[64], sph[64];
  int b = blockIdx.x, tid = threadIdx.x;
  int l = tid >> 3, sub = tid & 7;

  if (tid < 64) {
    sfr[tid] = freq[tid];
    sph[tid] = phase[tid];
  }
  {
    int h = tid >> 6, r = tid & 63, s2 = r >> 3, c = r & 7;
    int idx4;
    if (c < 4) idx4 = h * 64 + s2 * 4 + c;
    else if (c < 6) idx4 = h * 64 + 32 + s2 * 2 + (c - 4);
    else idx4 = h * 64 + 48 + s2 * 2 + (c - 6);
    float4 v = *(const float4*)&g_PR[(size_t)b * 1280 + (size_t)idx4 * 4];
    *(float4*)&p2[(h * 8 + s2) * 36 + c * 4] = v;
  }
  __syncthreads();

  float acc[4] = {0.f, 0.f, 0.f, 0.f};
  const float* xsrc = x_ctx + ((size_t)b * 32 + l) * 128 + sub * 16;
  float* kvrow = kv + l * 260;

#pragma unroll
  for (int c = 0; c < 4; c++) {
    float4 v = *(const float4*)&xsrc[c * 4];
    *(float4*)&kvrow[SW(sub * 16 + c * 4)] = v;
#pragma unroll
    for (int h = 0; h < 4; h++) {
      float4 p = *(const float4*)&p2[(h * 8 + sub) * 36 + c * 4];
      acc[h] = fmaf(v.x, p.x, acc[h]);
      acc[h] = fmaf(v.y, p.y, acc[h]);
      acc[h] = fmaf(v.z, p.z, acc[h]);
      acc[h] = fmaf(v.w, p.w, acc[h]);
    }
  }
  {
    float t = t_ctx[(size_t)b * 32 + l];
    float lt = log1pf(fmaxf(t, 0.f));
#pragma unroll
    for (int g = 0; g < 2; g++) {
      float4 sv, cv;
      float ss, cc;
      int k0 = sub * 8 + g * 4;
      float z0 = fmaf(lt, sfr[k0 + 0], sph[k0 + 0]);
      float z1 = fmaf(lt, sfr[k0 + 1], sph[k0 + 1]);
      float z2 = fmaf(lt, sfr[k0 + 2], sph[k0 + 2]);
      float z3 = fmaf(lt, sfr[k0 + 3], sph[k0 + 3]);
      fast_sincos(z0, ss, cc); sv.x = ss; cv.x = cc;
      fast_sincos(z1, ss, cc); sv.y = ss; cv.y = cc;
      fast_sincos(z2, ss, cc); sv.z = ss; cv.z = cc;
      fast_sincos(z3, ss, cc); sv.w = ss; cv.w = cc;
      *(float4*)&kvrow[SW(128 + sub * 8 + g * 4)] = sv;
      *(float4*)&kvrow[SW(192 + sub * 8 + g * 4)] = cv;
#pragma unroll
      for (int h = 0; h < 4; h++) {
        float4 ps = *(const float4*)&p2[(h * 8 + sub) * 36 + (4 + g) * 4];
        float4 pc = *(const float4*)&p2[(h * 8 + sub) * 36 + (6 + g) * 4];
        acc[h] = fmaf(sv.x, ps.x, acc[h]);
        acc[h] = fmaf(sv.y, ps.y, acc[h]);
        acc[h] = fmaf(sv.z, ps.z, acc[h]);
        acc[h] = fmaf(sv.w, ps.w, acc[h]);
        acc[h] = fmaf(cv.x, pc.x, acc[h]);
        acc[h] = fmaf(cv.y, pc.y, acc[h]);
        acc[h] = fmaf(cv.z, pc.z, acc[h]);
        acc[h] = fmaf(cv.w, pc.w, acc[h]);
      }
    }
  }
#pragma unroll
  for (int h = 0; h < 4; h++) {
#pragma unroll
    for (int o = 4; o; o >>= 1) acc[h] += __shfl_xor_sync(0xffffffffu, acc[h], o);
  }
  if (sub < 4) slog[sub * 32 + l] = acc[sub] * 0.125f;
  __syncthreads();
  if (tid < 128) {
    int h = tid >> 5, ll = tid & 31;
    float v = slog[tid];
    float m = wmax(v);
    float e = __expf(v - m);
    float s = wsum(e);
    sw[ll * 4 + h] = e / s;
  }
  __syncthreads();
  {
    int swt = SW(tid);
    unsigned long long a01 = 0ull, a23 = 0ull;
#pragma unroll
    for (int ll = 0; ll < 32; ll++) {
      ulonglong2 w2 = *(const ulonglong2*)&sw[ll * 4];
      unsigned long long vd = dup2(kv[ll * 260 + swt]);
      FMA2(a01, vd, w2.x);
      FMA2(a23, vd, w2.y);
    }
    float2 u01 = unpk(a01);
    float2 u23 = unpk(a23);
    size_t o = (size_t)b * 1024 + tid;
    uint32_t hh, ll2;
    split_tf32(u01.x, hh, ll2); g_Uh[o] = hh; g_Ul[o] = ll2;
    split_tf32(u01.y, hh, ll2); g_Uh[o + 256] = hh; g_Ul[o + 256] = ll2;
    split_tf32(u23.x, hh, ll2); g_Uh[o + 512] = hh; g_Ul[o + 512] = ll2;
    split_tf32(u23.y, hh, ll2); g_Uh[o + 768] = hh; g_Ul[o + 768] = ll2;
  }
}

// ---------------- LN: out = LN(S + resid + bias)*gamma + beta (+ planes) --------
template <bool EMIT>
__global__ void __launch_bounds__(256) ln_kernel(
    const float* __restrict__ S, const float* __restrict__ resid, int ldres,
    const float* __restrict__ bias, const float* __restrict__ gamma,
    const float* __restrict__ beta, float* __restrict__ out,
    uint32_t* __restrict__ outH, uint32_t* __restrict__ outL) {
  int row = blockIdx.x * 8 + (threadIdx.x >> 5);
  int lane = threadIdx.x & 31;
  int c0 = lane * 4, c1 = 128 + lane * 4;
  float4 a0 = *(const float4*)&S[(size_t)row * 256 + c0];
  float4 a1 = *(const float4*)&S[(size_t)row * 256 + c1];
  float4 r0 = *(const float4*)&resid[(size_t)row * ldres + c0];
  float4 r1 = *(const float4*)&resid[(size_t)row * ldres + c1];
  float4 b0 = *(const float4*)&bias[c0];
  float4 b1 = *(const float4*)&bias[c1];
  float v[8];
  v[0] = a0.x + r0.x + b0.x;
  v[1] = a0.y + r0.y + b0.y;
  v[2] = a0.z + r0.z + b0.z;
  v[3] = a0.w + r0.w + b0.w;
  v[4] = a1.x + r1.x + b1.x;
  v[5] = a1.y + r1.y + b1.y;
  v[6] = a1.z + r1.z + b1.z;
  v[7] = a1.w + r1.w + b1.w;
  float s = 0.f;
#pragma unroll
  for (int j = 0; j < 8; j++) s += v[j];
  s = wsum(s);
  float mean = s * (1.f / 256.f);
  float q = 0.f;
#pragma unroll
  for (int j = 0; j < 8; j++) {
    float d = v[j] - mean;
    q += d * d;
  }
  q = wsum(q);
  float rstd = rsqrtf(q * (1.f / 256.f) + 1e-5f);
  float4 g0 = *(const float4*)&gamma[c0];
  float4 g1 = *(const float4*)&gamma[c1];
  float4 e0 = *(const float4*)&beta[c0];
  float4 e1 = *(const float4*)&beta[c1];
  float o[8];
  o[0] = (v[0] - mean) * rstd * g0.x + e0.x;
  o[1] = (v[1] - mean) * rstd * g0.y + e0.y;
  o[2] = (v[2] - mean) * rstd * g0.z + e0.z;
  o[3] = (v[3] - mean) * rstd * g0.w + e0.w;
  o[4] = (v[4] - mean) * rstd * g1.x + e1.x;
  o[5] = (v[5] - mean) * rstd * g1.y + e1.y;
  o[6] = (v[6] - mean) * rstd * g1.z + e1.z;
  o[7] = (v[7] - mean) * rstd * g1.w + e1.w;
  float4 of0 = {o[0], o[1], o[2], o[3]};
  float4 of1 = {o[4], o[5], o[6], o[7]};
  *(float4*)&out[(size_t)row * 256 + c0] = of0;
  *(float4*)&out[(size_t)row * 256 + c1] = of1;
  if (EMIT) {
    uint4 h0, l0, h1, l1;
    split_tf32(o[0], h0.x, l0.x);
    split_tf32(o[1], h0.y, l0.y);
    split_tf32(o[2], h0.z, l0.z);
    split_tf32(o[3], h0.w, l0.w);
    split_tf32(o[4], h1.x, l1.x);
    split_tf32(o[5], h1.y, l1.y);
    split_tf32(o[6], h1.z, l1.z);
    split_tf32(o[7], h1.w, l1.w);
    *(uint4*)&outH[(size_t)row * 256 + c0] = h0;
    *(uint4*)&outL[(size_t)row * 256 + c0] = l0;
    *(uint4*)&outH[(size_t)row * 256 + c1] = h1;
    *(uint4*)&outL[(size_t)row * 256 + c1] = l1;
  }
}

// ---------------- launch ----------------
extern "C" void kernel_launch(void* const* d_in, const int* in_sizes, int n_in,
                              void* d_out, int out_size) {
  const float* x_u   = (const float*)d_in[0];
  const float* x_ctx = (const float*)d_in[1];
  const float* t_ctx = (const float*)d_in[2];
  const float* freq  = (const float*)d_in[3];
  const float* phase = (const float*)d_in[4];
  const float* Wq    = (const float*)d_in[5];
  const float* Wk    = (const float*)d_in[6];
  const float* Wv    = (const float*)d_in[7];
  const float* Wres  = (const float*)d_in[8];
  const float* bres  = (const float*)d_in[9];
  const float* W1    = (const float*)d_in[10];
  const float* b1    = (const float*)d_in[11];
  const float* W2    = (const float*)d_in[12];
  const float* b2    = (const float*)d_in[13];
  const float* g1    = (const float*)d_in[14];
  const float* be1   = (const float*)d_in[15];
  const float* g2    = (const float*)d_in[16];
  const float* be2   = (const float*)d_in[17];
  float* out = (float*)d_out;

  float *pPR, *pS, *pZ1;
  uint32_t *pXh, *pXl, *pWcatH, *pWcatL, *pWvH, *pWvL, *pW1H, *pW1L, *pW2H, *pW2L;
  uint32_t *pUh, *pUl, *pZ1h, *pZ1l, *pH1h, *pH1l;
  cudaGetSymbolAddress((void**)&pPR, g_PR);
  cudaGetSymbolAddress((void**)&pS, g_S);
  cudaGetSymbolAddress((void**)&pZ1, g_Z1);
  cudaGetSymbolAddress((void**)&pXh, g_Xh);
  cudaGetSymbolAddress((void**)&pXl, g_Xl);
  cudaGetSymbolAddress((void**)&pWcatH, g_WcatH);
  cudaGetSymbolAddress((void**)&pWcatL, g_WcatL);
  cudaGetSymbolAddress((void**)&pWvH, g_WvH);
  cudaGetSymbolAddress((void**)&pWvL, g_WvL);
  cudaGetSymbolAddress((void**)&pW1H, g_W1H);
  cudaGetSymbolAddress((void**)&pW1L, g_W1L);
  cudaGetSymbolAddress((void**)&pW2H, g_W2H);
  cudaGetSymbolAddress((void**)&pW2L, g_W2L);
  cudaGetSymbolAddress((void**)&pUh, g_Uh);
  cudaGetSymbolAddress((void**)&pUl, g_Ul);
  cudaGetSymbolAddress((void**)&pZ1h, g_Z1h);
  cudaGetSymbolAddress((void**)&pZ1l, g_Z1l);
  cudaGetSymbolAddress((void**)&pH1h, g_H1h);
  cudaGetSymbolAddress((void**)&pH1l, g_H1l);

  int smem8 = (2 * 64 * 36 + 2 * 32 * 136) * 4;  // 53,248 B
  int smem4 = (2 * 64 * 36 + 2 * 32 * 72) * 4;   // 36,864 B
  cudaFuncSetAttribute(gemm_tc<8, 0>, cudaFuncAttributeMaxDynamicSharedMemorySize, smem8);
  cudaFuncSetAttribute(gemm_tc<8, 1>, cudaFuncAttributeMaxDynamicSharedMemorySize, smem8);
  cudaFuncSetAttribute(gemm_tc<4, 0>, cudaFuncAttributeMaxDynamicSharedMemorySize, smem4);

  // prep: convert operands to tf32 planes
  cvt_pl<<<(BB * 128 / 4 + 255) / 256, 256>>>(x_u, pXh, pXl, BB * 128 / 4);
  cvt_pl<<<64, 256>>>(Wv, pWvH, pWvL, 256 * 256 / 4);
  cvt_pl<<<64, 256>>>(W1, pW1H, pW1L, 256 * 256 / 4);
  cvt_pl<<<64, 256>>>(W2, pW2H, pW2L, 256 * 256 / 4);
  mqk_kernel<<<dim3(4, 8), 256>>>(Wq, Wk);
  copy_wres_kernel<<<128, 256>>>(Wres);

  // K1: P|R = x_u @ Wcat
  gemm_tc<8, 0><<<dim3(10, 256, 1), 128, smem8>>>(
      pXh, pXl, 128, 0, pWcatH, pWcatL, 1280, 0,
      pPR, nullptr, nullptr, 1280, 0, 128, nullptr);

  // K2: attention -> u planes
  attn_u_kernel<<<BB, 256>>>(x_ctx, t_ctx, freq, phase);

  // K3: S = u_h @ Wv_h (per head via z); z1 = LN(S + R + bres)
  gemm_tc<4, 0><<<dim3(1, 256, 4), 128, smem4>>>(
      pUh, pUl, 1024, 256, pWvH, pWvL, 256, 64,
      pS, nullptr, nullptr, 256, 64, 256, nullptr);
  ln_kernel<true><<<BB / 8, 256>>>(pS, pPR + 1024, 1280, bres, g1, be1, pZ1, pZ1h, pZ1l);

  // K4: h1 = relu(z1 @ W1 + b1) -> planes
  gemm_tc<8, 1><<<dim3(2, 256, 1), 128, smem8>>>(
      pZ1h, pZ1l, 256, 0, pW1H, pW1L, 256, 0,
      nullptr, pH1h, pH1l, 256, 0, 256, b1);

  // K5: S = h1 @ W2 ; out = LN(S + z1 + b2)
  gemm_tc<8, 0><<<dim3(2, 256, 1), 128, smem8>>>(
      pH1h, pH1l, 256, 0, pW2H, pW2L, 256, 0,
      pS, nullptr, nullptr, 256, 0, 256, nullptr);
  ln_kernel<false><<<BB / 8, 256>>>(pS, pZ1, 256, b2, g2, be2, out, nullptr, nullptr);
}

// round 11
// speedup vs baseline: 1.1026x; 1.0997x over previous
#include <cuda_runtime.h>
#include <math.h>
#include <stdint.h>

#define BB 16384

__device__ __align__(16) float g_Wcat[128 * 1280];
__device__ __align__(16) float g_PR[(size_t)BB * 1280];
__device__ __align__(16) float g_U[(size_t)BB * 1024];
__device__ __align__(16) float g_S[(size_t)BB * 256];
__device__ __align__(16) float g_Z1[(size_t)BB * 256];
__device__ __align__(16) float g_H1[(size_t)BB * 256];

__device__ __forceinline__ float wsum(float v) {
#pragma unroll
  for (int o = 16; o; o >>= 1) v += __shfl_xor_sync(0xffffffffu, v, o);
  return v;
}
__device__ __forceinline__ float wmax(float v) {
#pragma unroll
  for (int o = 16; o; o >>= 1) v = fmaxf(v, __shfl_xor_sync(0xffffffffu, v, o));
  return v;
}

#define FMA2(d, a, b) \
  asm("fma.rn.f32x2 %0, %1, %2, %0;" : "+l"(d) : "l"(a), "l"(b))
__device__ __forceinline__ unsigned long long dup2(float x) {
  unsigned long long r;
  asm("mov.b64 %0, {%1, %1};" : "=l"(r) : "f"(x));
  return r;
}
__device__ __forceinline__ float2 unpk(unsigned long long p) {
  float2 r;
  asm("mov.b64 {%0, %1}, %2;" : "=f"(r.x), "=f"(r.y) : "l"(p));
  return r;
}
__device__ __forceinline__ void cpa16(uint32_t s, const void* g) {
  asm volatile("cp.async.cg.shared.global [%0], [%1], 16;" :: "r"(s), "l"(g));
}
#define CP_COMMIT() asm volatile("cp.async.commit_group;" ::: "memory")
#define CP_WAIT0() asm volatile("cp.async.wait_group 0;" ::: "memory")

__device__ __forceinline__ int SW(int d) {
  return (d & ~31) | ((d & 31) ^ (((d >> 5) & 3) << 2));
}

__device__ __forceinline__ void fast_sincos(float z, float& s, float& c) {
  float t = rintf(z * 0.63661977236758134f);
  int qi = (int)t;
  float r = fmaf(t, -1.5703125f, z);
  r = fmaf(t, -4.83751296997070312e-4f, r);
  r = fmaf(t, -7.54978995489188e-8f, r);
  float r2 = r * r;
  float sp = fmaf(r2, -1.9515296e-4f, 8.3321608e-3f);
  sp = fmaf(r2, sp, -1.6666654611e-1f);
  float sinr = fmaf(r * r2, sp, r);
  float cp = fmaf(r2, -1.388731625493765e-3f, 4.166664568298827e-2f);
  cp = fmaf(r2, cp, -0.5f);
  float cosr = fmaf(r2, cp, 1.0f);
  int qq = qi & 3;
  float ss = (qq & 1) ? cosr : sinr;
  float cc = (qq & 1) ? sinr : cosr;
  s = (qq & 2) ? -ss : ss;
  c = ((qq + 1) & 2) ? -cc : cc;
}

// ---------------- K0 ----------------
__global__ void __launch_bounds__(256) mqk_kernel(const float* __restrict__ Wq,
                                                  const float* __restrict__ Wk) {
  __shared__ float sWq[16 * 68];
  __shared__ float sWk[128 * 68];
  int h = blockIdx.x, is = blockIdx.y, tid = threadIdx.x;
  {
    int il = tid >> 4, d4 = tid & 15;
    *(float4*)&sWq[il * 68 + d4 * 4] =
        *(const float4*)&Wq[(size_t)(is * 16 + il) * 256 + h * 64 + d4 * 4];
  }
  for (int jc = 0; jc < 2; jc++) {
    __syncthreads();
#pragma unroll
    for (int it = 0; it < 8; it++) {
      int f = tid + it * 256, j = f >> 4, d4 = f & 15;
      *(float4*)&sWk[j * 68 + d4 * 4] =
          *(const float4*)&Wk[(size_t)(jc * 128 + j) * 256 + h * 64 + d4 * 4];
    }
    __syncthreads();
    int j = tid & 127, ih = tid >> 7;
#pragma unroll 1
    for (int il = ih * 8; il < ih * 8 + 8; il++) {
      float acc = 0.f;
#pragma unroll
      for (int d = 0; d < 64; d++) acc = fmaf(sWq[il * 68 + d], sWk[j * 68 + d], acc);
      g_Wcat[(size_t)(is * 16 + il) * 1280 + h * 256 + jc * 128 + j] = acc;
    }
  }
}

__global__ void copy_wres_kernel(const float* __restrict__ Wres) {
  g_Wcat[(size_t)blockIdx.x * 1280 + 1024 + threadIdx.x] =
      Wres[(size_t)blockIdx.x * 256 + threadIdx.x];
}

// ---------- SIMT GEMM, cp.async double-buffered, warp tile 16x128 ----------
template <int EPI>  // 0 store, 1 relu(x+bias)
__global__ void __launch_bounds__(256, 2) gemm_epi(
    const float* __restrict__ A, const float* __restrict__ W, float* __restrict__ C,
    int K, int ldw, int ldc, const float* __restrict__ bias) {
  extern __shared__ float smd[];
  float* sAT = smd;                 // [2][32*68]
  float* sB = smd + 2 * 32 * 68;    // [2][32*256]
  int tid = threadIdx.x, lane = tid & 31, wid = tid >> 5;
  int rbase = (wid >> 1) * 16;
  int cb = (wid & 1) * 128 + lane * 4;
  int m0 = blockIdx.y * 64, n0 = blockIdx.x * 256;
  unsigned long long acc[8][4];
#pragma unroll
  for (int i = 0; i < 8; i++)
#pragma unroll
    for (int j = 0; j < 4; j++) acc[i][j] = 0ull;

  int af = tid >> 3 << 0, ar = tid >> 3, akq = tid & 7;  // for A loads (it stride 256)
  uint32_t sBu = (uint32_t)__cvta_generic_to_shared(sB);
  int kt_n = K >> 5;
  float4 aR[2];

  // prologue tile 0
#pragma unroll
  for (int it = 0; it < 8; it++) {
    int f = tid + it * 256, kk = f >> 6, c4 = f & 63;
    cpa16(sBu + (kk * 256 + c4 * 4) * 4, &W[(size_t)kk * ldw + n0 + c4 * 4]);
  }
  CP_COMMIT();
#pragma unroll
  for (int it = 0; it < 2; it++) {
    int f = tid + it * 256, r = f >> 3, kq = f & 7;
    aR[it] = *(const float4*)&A[(size_t)(m0 + r) * K + kq * 4];
  }
#pragma unroll
  for (int it = 0; it < 2; it++) {
    int f = tid + it * 256, r = f >> 3, kq = f & 7;
    sAT[(kq * 4 + 0) * 68 + r] = aR[it].x;
    sAT[(kq * 4 + 1) * 68 + r] = aR[it].y;
    sAT[(kq * 4 + 2) * 68 + r] = aR[it].z;
    sAT[(kq * 4 + 3) * 68 + r] = aR[it].w;
  }
  CP_WAIT0();
  __syncthreads();

  for (int kt = 0; kt < kt_n; kt++) {
    int nb = (kt + 1) & 1;
    if (kt + 1 < kt_n) {
#pragma unroll
      for (int it = 0; it < 8; it++) {
        int f = tid + it * 256, kk = f >> 6, c4 = f & 63;
        cpa16(sBu + (nb * 32 * 256 + kk * 256 + c4 * 4) * 4,
              &W[(size_t)((kt + 1) * 32 + kk) * ldw + n0 + c4 * 4]);
      }
      CP_COMMIT();
#pragma unroll
      for (int it = 0; it < 2; it++) {
        int f = tid + it * 256, r = f >> 3, kq = f & 7;
        aR[it] = *(const float4*)&A[(size_t)(m0 + r) * K + (kt + 1) * 32 + kq * 4];
      }
    }
    const float* cA = sAT + (kt & 1) * 32 * 68;
    const float* cB = sB + (kt & 1) * 32 * 256;
#pragma unroll
    for (int kk = 0; kk < 32; kk++) {
      float4 bv = *(const float4*)&cB[kk * 256 + cb];
      unsigned long long bd0 = dup2(bv.x), bd1 = dup2(bv.y);
      unsigned long long bd2 = dup2(bv.z), bd3 = dup2(bv.w);
      const ulonglong2* ap = (const ulonglong2*)&cA[kk * 68 + rbase];
      ulonglong2 p0 = ap[0], p1 = ap[1], p2 = ap[2], p3 = ap[3];
      unsigned long long arr[8] = {p0.x, p0.y, p1.x, p1.y, p2.x, p2.y, p3.x, p3.y};
#pragma unroll
      for (int rp = 0; rp < 8; rp++) {
        FMA2(acc[rp][0], arr[rp], bd0);
        FMA2(acc[rp][1], arr[rp], bd1);
        FMA2(acc[rp][2], arr[rp], bd2);
        FMA2(acc[rp][3], arr[rp], bd3);
      }
    }
    if (kt + 1 < kt_n) {
      float* nA = sAT + nb * 32 * 68;
#pragma unroll
      for (int it = 0; it < 2; it++) {
        int f = tid + it * 256, r = f >> 3, kq = f & 7;
        nA[(kq * 4 + 0) * 68 + r] = aR[it].x;
        nA[(kq * 4 + 1) * 68 + r] = aR[it].y;
        nA[(kq * 4 + 2) * 68 + r] = aR[it].z;
        nA[(kq * 4 + 3) * 68 + r] = aR[it].w;
      }
      CP_WAIT0();
      __syncthreads();
    }
  }
  float bb[4];
  if (EPI == 1) {
    float4 bv = *(const float4*)&bias[n0 + cb];
    bb[0] = bv.x; bb[1] = bv.y; bb[2] = bv.z; bb[3] = bv.w;
  }
#pragma unroll
  for (int rp = 0; rp < 8; rp++) {
    float2 c0v = unpk(acc[rp][0]), c1v = unpk(acc[rp][1]);
    float2 c2v = unpk(acc[rp][2]), c3v = unpk(acc[rp][3]);
    float4 o0 = {c0v.x, c1v.x, c2v.x, c3v.x};
    float4 o1 = {c0v.y, c1v.y, c2v.y, c3v.y};
    if (EPI == 1) {
      o0.x = fmaxf(o0.x + bb[0], 0.f); o0.y = fmaxf(o0.y + bb[1], 0.f);
      o0.z = fmaxf(o0.z + bb[2], 0.f); o0.w = fmaxf(o0.w + bb[3], 0.f);
      o1.x = fmaxf(o1.x + bb[0], 0.f); o1.y = fmaxf(o1.y + bb[1], 0.f);
      o1.z = fmaxf(o1.z + bb[2], 0.f); o1.w = fmaxf(o1.w + bb[3], 0.f);
    }
    *(float4*)&C[(size_t)(m0 + rbase + 2 * rp) * ldc + n0 + cb] = o0;
    *(float4*)&C[(size_t)(m0 + rbase + 2 * rp + 1) * ldc + n0 + cb] = o1;
  }
}

// ---------- K3: head-split GEMM, cp.async double-buffered ----------
__global__ void __launch_bounds__(256, 2) gemm_hs(
    const float* __restrict__ Wv, float* __restrict__ C) {
  extern __shared__ float smd[];
  float* sAT = smd;                     // [2][16*4*68]
  float* sB = smd + 2 * 16 * 4 * 68;    // [2][16*256]
  int tid = threadIdx.x, lane = tid & 31, wid = tid >> 5;
  int rbase = (wid >> 1) * 16;
  int colslab = wid & 1;
  int cb = colslab * 128 + lane * 4;
  int hl = colslab * 2 + (lane >> 4);
  int m0 = blockIdx.y * 64;
  unsigned long long acc[8][4];
#pragma unroll
  for (int i = 0; i < 8; i++)
#pragma unroll
    for (int j = 0; j < 4; j++) acc[i][j] = 0ull;

  uint32_t sBu = (uint32_t)__cvta_generic_to_shared(sB);
  float4 aR[4];
#pragma unroll
  for (int it = 0; it < 4; it++) {
    int f = tid + it * 256, kk = f >> 6, c4 = f & 63;
    cpa16(sBu + (kk * 256 + c4 * 4) * 4, &Wv[(size_t)kk * 256 + c4 * 4]);
  }
  CP_COMMIT();
#pragma unroll
  for (int it = 0; it < 4; it++) {
    int f = tid + it * 256, r = f >> 4, q = f & 15, h = q >> 2, kq = q & 3;
    aR[it] = *(const float4*)&g_U[(size_t)(m0 + r) * 1024 + h * 256 + kq * 4];
  }
#pragma unroll
  for (int it = 0; it < 4; it++) {
    int f = tid + it * 256, r = f >> 4, q = f & 15, h = q >> 2, kq = q & 3;
    sAT[((kq * 4 + 0) * 4 + h) * 68 + r] = aR[it].x;
    sAT[((kq * 4 + 1) * 4 + h) * 68 + r] = aR[it].y;
    sAT[((kq * 4 + 2) * 4 + h) * 68 + r] = aR[it].z;
    sAT[((kq * 4 + 3) * 4 + h) * 68 + r] = aR[it].w;
  }
  CP_WAIT0();
  __syncthreads();

  for (int kt = 0; kt < 16; kt++) {
    int nb = (kt + 1) & 1;
    if (kt + 1 < 16) {
#pragma unroll
      for (int it = 0; it < 4; it++) {
        int f = tid + it * 256, kk = f >> 6, c4 = f & 63;
        cpa16(sBu + (nb * 16 * 256 + kk * 256 + c4 * 4) * 4,
              &Wv[(size_t)((kt + 1) * 16 + kk) * 256 + c4 * 4]);
      }
      CP_COMMIT();
#pragma unroll
      for (int it = 0; it < 4; it++) {
        int f = tid + it * 256, r = f >> 4, q = f & 15, h = q >> 2, kq = q & 3;
        aR[it] = *(const float4*)&g_U[(size_t)(m0 + r) * 1024 + h * 256 +
                                      (kt + 1) * 16 + kq * 4];
      }
    }
    const float* cA = sAT + (kt & 1) * 16 * 4 * 68;
    const float* cB = sB + (kt & 1) * 16 * 256;
#pragma unroll
    for (int kk = 0; kk < 16; kk++) {
      float4 bv = *(const float4*)&cB[kk * 256 + cb];
      unsigned long long bd0 = dup2(bv.x), bd1 = dup2(bv.y);
      unsigned long long bd2 = dup2(bv.z), bd3 = dup2(bv.w);
      const ulonglong2* ap = (const ulonglong2*)&cA[(kk * 4 + hl) * 68 + rbase];
      ulonglong2 p0 = ap[0], p1 = ap[1], p2 = ap[2], p3 = ap[3];
      unsigned long long arr[8] = {p0.x, p0.y, p1.x, p1.y, p2.x, p2.y, p3.x, p3.y};
#pragma unroll
      for (int rp = 0; rp < 8; rp++) {
        FMA2(acc[rp][0], arr[rp], bd0);
        FMA2(acc[rp][1], arr[rp], bd1);
        FMA2(acc[rp][2], arr[rp], bd2);
        FMA2(acc[rp][3], arr[rp], bd3);
      }
    }
    if (kt + 1 < 16) {
      float* nA = sAT + nb * 16 * 4 * 68;
#pragma unroll
      for (int it = 0; it < 4; it++) {
        int f = tid + it * 256, r = f >> 4, q = f & 15, h = q >> 2, kq = q & 3;
        nA[((kq * 4 + 0) * 4 + h) * 68 + r] = aR[it].x;
        nA[((kq * 4 + 1) * 4 + h) * 68 + r] = aR[it].y;
        nA[((kq * 4 + 2) * 4 + h) * 68 + r] = aR[it].z;
        nA[((kq * 4 + 3) * 4 + h) * 68 + r] = aR[it].w;
      }
      CP_WAIT0();
      __syncthreads();
    }
  }
#pragma unroll
  for (int rp = 0; rp < 8; rp++) {
    float2 c0v = unpk(acc[rp][0]), c1v = unpk(acc[rp][1]);
    float2 c2v = unpk(acc[rp][2]), c3v = unpk(acc[rp][3]);
    float4 o0 = {c0v.x, c1v.x, c2v.x, c3v.x};
    float4 o1 = {c0v.y, c1v.y, c2v.y, c3v.y};
    *(float4*)&C[(size_t)(m0 + rbase + 2 * rp) * 256 + cb] = o0;
    *(float4*)&C[(size_t)(m0 + rbase + 2 * rp + 1) * 256 + cb] = o1;
  }
}

// ---------------- K2: attention (R6-proven) ----------------
__global__ void __launch_bounds__(256) attn_u_kernel(
    const float* __restrict__ x_ctx, const float* __restrict__ t_ctx,
    const float* __restrict__ freq, const float* __restrict__ phase) {
  __shared__ float kv[32 * 260];
  __shared__ float p2[4 * 8 * 36];
  __shared__ float slog[128];
  __shared__ __align__(16) float sw[128];
  __shared__ float sfr[64], sph[64];
  int b = blockIdx.x, tid = threadIdx.x;
  int l = tid >> 3, sub = tid & 7;

  if (tid < 64) {
    sfr[tid] = freq[tid];
    sph[tid] = phase[tid];
  }
  {
    int h = tid >> 6, r = tid & 63, s2 = r >> 3, c = r & 7;
    int idx4;
    if (c < 4) idx4 = h * 64 + s2 * 4 + c;
    else if (c < 6) idx4 = h * 64 + 32 + s2 * 2 + (c - 4);
    else idx4 = h * 64 + 48 + s2 * 2 + (c - 6);
    float4 v = *(const float4*)&g_PR[(size_t)b * 1280 + (size_t)idx4 * 4];
    *(float4*)&p2[(h * 8 + s2) * 36 + c * 4] = v;
  }
  __syncthreads();

  float acc[4] = {0.f, 0.f, 0.f, 0.f};
  const float* xsrc = x_ctx + ((size_t)b * 32 + l) * 128 + sub * 16;
  float* kvrow = kv + l * 260;

#pragma unroll
  for (int c = 0; c < 4; c++) {
    float4 v = *(const float4*)&xsrc[c * 4];
    *(float4*)&kvrow[SW(sub * 16 + c * 4)] = v;
#pragma unroll
    for (int h = 0; h < 4; h++) {
      float4 p = *(const float4*)&p2[(h * 8 + sub) * 36 + c * 4];
      acc[h] = fmaf(v.x, p.x, acc[h]);
      acc[h] = fmaf(v.y, p.y, acc[h]);
      acc[h] = fmaf(v.z, p.z, acc[h]);
      acc[h] = fmaf(v.w, p.w, acc[h]);
    }
  }
  {
    float t = t_ctx[(size_t)b * 32 + l];
    float lt = log1pf(fmaxf(t, 0.f));
#pragma unroll
    for (int g = 0; g < 2; g++) {
      float4 sv, cv;
      float ss, cc;
      int k0 = sub * 8 + g * 4;
      float z0 = fmaf(lt, sfr[k0 + 0], sph[k0 + 0]);
      float z1 = fmaf(lt, sfr[k0 + 1], sph[k0 + 1]);
      float z2 = fmaf(lt, sfr[k0 + 2], sph[k0 + 2]);
      float z3 = fmaf(lt, sfr[k0 + 3], sph[k0 + 3]);
      fast_sincos(z0, ss, cc); sv.x = ss; cv.x = cc;
      fast_sincos(z1, ss, cc); sv.y = ss; cv.y = cc;
      fast_sincos(z2, ss, cc); sv.z = ss; cv.z = cc;
      fast_sincos(z3, ss, cc); sv.w = ss; cv.w = cc;
      *(float4*)&kvrow[SW(128 + sub * 8 + g * 4)] = sv;
      *(float4*)&kvrow[SW(192 + sub * 8 + g * 4)] = cv;
#pragma unroll
      for (int h = 0; h < 4; h++) {
        float4 ps = *(const float4*)&p2[(h * 8 + sub) * 36 + (4 + g) * 4];
        float4 pc = *(const float4*)&p2[(h * 8 + sub) * 36 + (6 + g) * 4];
        acc[h] = fmaf(sv.x, ps.x, acc[h]);
        acc[h] = fmaf(sv.y, ps.y, acc[h]);
        acc[h] = fmaf(sv.z, ps.z, acc[h]);
        acc[h] = fmaf(sv.w, ps.w, acc[h]);
        acc[h] = fmaf(cv.x, pc.x, acc[h]);
        acc[h] = fmaf(cv.y, pc.y, acc[h]);
        acc[h] = fmaf(cv.z, pc.z, acc[h]);
        acc[h] = fmaf(cv.w, pc.w, acc[h]);
      }
    }
  }
#pragma unroll
  for (int h = 0; h < 4; h++) {
#pragma unroll
    for (int o = 4; o; o >>= 1) acc[h] += __shfl_xor_sync(0xffffffffu, acc[h], o);
  }
  if (sub < 4) slog[sub * 32 + l] = acc[sub] * 0.125f;
  __syncthreads();
  if (tid < 128) {
    int h = tid >> 5, ll = tid & 31;
    float v = slog[tid];
    float m = wmax(v);
    float e = __expf(v - m);
    float s = wsum(e);
    sw[ll * 4 + h] = e / s;
  }
  __syncthreads();
  {
    int swt = SW(tid);
    unsigned long long a01 = 0ull, a23 = 0ull;
#pragma unroll
    for (int ll = 0; ll < 32; ll++) {
      ulonglong2 w2 = *(const ulonglong2*)&sw[ll * 4];
      unsigned long long vd = dup2(kv[ll * 260 + swt]);
      FMA2(a01, vd, w2.x);
      FMA2(a23, vd, w2.y);
    }
    float2 u01 = unpk(a01);
    float2 u23 = unpk(a23);
    size_t o = (size_t)b * 1024 + tid;
    g_U[o] = u01.x;
    g_U[o + 256] = u01.y;
    g_U[o + 512] = u23.x;
    g_U[o + 768] = u23.y;
  }
}

// ---------------- LN ----------------
__global__ void __launch_bounds__(256) ln_kernel(
    const float* __restrict__ S, const float* __restrict__ resid, int ldres,
    const float* __restrict__ bias, const float* __restrict__ gamma,
    const float* __restrict__ beta, float* __restrict__ out) {
  int row = blockIdx.x * 8 + (threadIdx.x >> 5);
  int lane = threadIdx.x & 31;
  int c0 = lane * 4, c1 = 128 + lane * 4;
  float4 a0 = *(const float4*)&S[(size_t)row * 256 + c0];
  float4 a1 = *(const float4*)&S[(size_t)row * 256 + c1];
  float4 r0 = *(const float4*)&resid[(size_t)row * ldres + c0];
  float4 r1 = *(const float4*)&resid[(size_t)row * ldres + c1];
  float4 b0 = *(const float4*)&bias[c0];
  float4 b1 = *(const float4*)&bias[c1];
  float v[8];
  v[0] = a0.x + r0.x + b0.x; v[1] = a0.y + r0.y + b0.y;
  v[2] = a0.z + r0.z + b0.z; v[3] = a0.w + r0.w + b0.w;
  v[4] = a1.x + r1.x + b1.x; v[5] = a1.y + r1.y + b1.y;
  v[6] = a1.z + r1.z + b1.z; v[7] = a1.w + r1.w + b1.w;
  float s = 0.f;
#pragma unroll
  for (int j = 0; j < 8; j++) s += v[j];
  s = wsum(s);
  float mean = s * (1.f / 256.f);
  float q = 0.f;
#pragma unroll
  for (int j = 0; j < 8; j++) {
    float d = v[j] - mean;
    q += d * d;
  }
  q = wsum(q);
  float rstd = rsqrtf(q * (1.f / 256.f) + 1e-5f);
  float4 g0 = *(const float4*)&gamma[c0];
  float4 g1 = *(const float4*)&gamma[c1];
  float4 e0 = *(const float4*)&beta[c0];
  float4 e1 = *(const float4*)&beta[c1];
  float4 o0, o1;
  o0.x = (v[0] - mean) * rstd * g0.x + e0.x;
  o0.y = (v[1] - mean) * rstd * g0.y + e0.y;
  o0.z = (v[2] - mean) * rstd * g0.z + e0.z;
  o0.w = (v[3] - mean) * rstd * g0.w + e0.w;
  o1.x = (v[4] - mean) * rstd * g1.x + e1.x;
  o1.y = (v[5] - mean) * rstd * g1.y + e1.y;
  o1.z = (v[6] - mean) * rstd * g1.z + e1.z;
  o1.w = (v[7] - mean) * rstd * g1.w + e1.w;
  *(float4*)&out[(size_t)row * 256 + c0] = o0;
  *(float4*)&out[(size_t)row * 256 + c1] = o1;
}

// ---------------- launch ----------------
extern "C" void kernel_launch(void* const* d_in, const int* in_sizes, int n_in,
                              void* d_out, int out_size) {
  const float* x_u   = (const float*)d_in[0];
  const float* x_ctx = (const float*)d_in[1];
  const float* t_ctx = (const float*)d_in[2];
  const float* freq  = (const float*)d_in[3];
  const float* phase = (const float*)d_in[4];
  const float* Wq    = (const float*)d_in[5];
  const float* Wk    = (const float*)d_in[6];
  const float* Wv    = (const float*)d_in[7];
  const float* Wres  = (const float*)d_in[8];
  const float* bres  = (const float*)d_in[9];
  const float* W1    = (const float*)d_in[10];
  const float* b1    = (const float*)d_in[11];
  const float* W2    = (const float*)d_in[12];
  const float* b2    = (const float*)d_in[13];
  const float* g1    = (const float*)d_in[14];
  const float* be1   = (const float*)d_in[15];
  const float* g2    = (const float*)d_in[16];
  const float* be2   = (const float*)d_in[17];
  float* out = (float*)d_out;

  float *pWcat, *pPR, *pS, *pZ1, *pH1;
  cudaGetSymbolAddress((void**)&pWcat, g_Wcat);
  cudaGetSymbolAddress((void**)&pPR, g_PR);
  cudaGetSymbolAddress((void**)&pS, g_S);
  cudaGetSymbolAddress((void**)&pZ1, g_Z1);
  cudaGetSymbolAddress((void**)&pH1, g_H1);

  int smemEpi = (2 * 32 * 68 + 2 * 32 * 256) * 4;   // 82,944 B
  int smemHs = (2 * 16 * 4 * 68 + 2 * 16 * 256) * 4;  // 67,584 B
  cudaFuncSetAttribute(gemm_epi<0>, cudaFuncAttributeMaxDynamicSharedMemorySize, smemEpi);
  cudaFuncSetAttribute(gemm_epi<1>, cudaFuncAttributeMaxDynamicSharedMemorySize, smemEpi);
  cudaFuncSetAttribute(gemm_hs, cudaFuncAttributeMaxDynamicSharedMemorySize, smemHs);

  mqk_kernel<<<dim3(4, 8), 256>>>(Wq, Wk);
  copy_wres_kernel<<<128, 256>>>(Wres);

  // K1: P|R = x_u @ Wcat
  gemm_epi<0><<<dim3(5, 256), 256, smemEpi>>>(x_u, pWcat, pPR, 128, 1280, 1280, nullptr);

  // K2: attention -> u
  attn_u_kernel<<<BB, 256>>>(x_ctx, t_ctx, freq, phase);

  // K3: S = u_h @ Wv_h ; z1 = LN(S + R + bres)
  gemm_hs<<<dim3(1, 256), 256, smemHs>>>(Wv, pS);
  ln_kernel<<<BB / 8, 256>>>(pS, pPR + 1024, 1280, bres, g1, be1, pZ1);

  // K4: h1 = relu(z1 @ W1 + b1)
  gemm_epi<1><<<dim3(1, 256), 256, smemEpi>>>(pZ1, W1, pH1, 256, 256, 256, b1);

  // K5: S = h1 @ W2 ; out = LN(S + z1 + b2)
  gemm_epi<0><<<dim3(1, 256), 256, smemEpi>>>(pH1, W2, pS, 256, 256, 256, nullptr);
  ln_kernel<<<BB / 8, 256>>>(pS, pZ1, 256, b2, g2, be2, out);
}

// round 12
// speedup vs baseline: 1.1489x; 1.0420x over previous
#include <cuda_runtime.h>
#include <math.h>
#include <stdint.h>

#define BB 16384

__device__ __align__(16) float g_Wcat[128 * 1280];
__device__ __align__(16) float g_PR[(size_t)BB * 1280];
__device__ __align__(16) float g_U[(size_t)BB * 1024];
__device__ __align__(16) float g_Z1[(size_t)BB * 256];
__device__ __align__(16) float g_H1[(size_t)BB * 256];

__device__ __forceinline__ float wsum(float v) {
#pragma unroll
  for (int o = 16; o; o >>= 1) v += __shfl_xor_sync(0xffffffffu, v, o);
  return v;
}
__device__ __forceinline__ float wmax(float v) {
#pragma unroll
  for (int o = 16; o; o >>= 1) v = fmaxf(v, __shfl_xor_sync(0xffffffffu, v, o));
  return v;
}

#define FMA2(d, a, b) \
  asm("fma.rn.f32x2 %0, %1, %2, %0;" : "+l"(d) : "l"(a), "l"(b))
__device__ __forceinline__ unsigned long long dup2(float x) {
  unsigned long long r;
  asm("mov.b64 %0, {%1, %1};" : "=l"(r) : "f"(x));
  return r;
}
__device__ __forceinline__ float2 unpk(unsigned long long p) {
  float2 r;
  asm("mov.b64 {%0, %1}, %2;" : "=f"(r.x), "=f"(r.y) : "l"(p));
  return r;
}
__device__ __forceinline__ void cpa16(uint32_t s, const void* g) {
  asm volatile("cp.async.cg.shared.global [%0], [%1], 16;" :: "r"(s), "l"(g));
}
#define CP_COMMIT() asm volatile("cp.async.commit_group;" ::: "memory")
#define CP_WAIT0() asm volatile("cp.async.wait_group 0;" ::: "memory")

__device__ __forceinline__ int SW(int d) {
  return (d & ~31) | ((d & 31) ^ (((d >> 5) & 3) << 2));
}

__device__ __forceinline__ void fast_sincos(float z, float& s, float& c) {
  float t = rintf(z * 0.63661977236758134f);
  int qi = (int)t;
  float r = fmaf(t, -1.5703125f, z);
  r = fmaf(t, -4.83751296997070312e-4f, r);
  r = fmaf(t, -7.54978995489188e-8f, r);
  float r2 = r * r;
  float sp = fmaf(r2, -1.9515296e-4f, 8.3321608e-3f);
  sp = fmaf(r2, sp, -1.6666654611e-1f);
  float sinr = fmaf(r * r2, sp, r);
  float cp = fmaf(r2, -1.388731625493765e-3f, 4.166664568298827e-2f);
  cp = fmaf(r2, cp, -0.5f);
  float cosr = fmaf(r2, cp, 1.0f);
  int qq = qi & 3;
  float ss = (qq & 1) ? cosr : sinr;
  float cc = (qq & 1) ? sinr : cosr;
  s = (qq & 2) ? -ss : ss;
  c = ((qq + 1) & 2) ? -cc : cc;
}

// per-warp LN helper: v[16][4] rows rbase.., cols cb..cb+3; cross-slab via red arrays
__device__ __forceinline__ void ln_epilogue(
    float (*v)[4], int rbase, int colslab, int cb,
    float* redS, float* redQ,  // [2][64] each
    const float* gamma, const float* beta, float* C, int ldc, size_t m0) {
  int lane = threadIdx.x & 31;
#pragma unroll
  for (int r = 0; r < 16; r++) {
    float s = v[r][0] + v[r][1] + v[r][2] + v[r][3];
    float q = v[r][0] * v[r][0] + v[r][1] * v[r][1] +
              v[r][2] * v[r][2] + v[r][3] * v[r][3];
    s = wsum(s);
    q = wsum(q);
    if (lane == 0) {
      redS[colslab * 64 + rbase + r] = s;
      redQ[colslab * 64 + rbase + r] = q;
    }
  }
  __syncthreads();
  float4 gg = *(const float4*)&gamma[cb];
  float4 ee = *(const float4*)&beta[cb];
#pragma unroll
  for (int r = 0; r < 16; r++) {
    float s = redS[rbase + r] + redS[64 + rbase + r];
    float q = redQ[rbase + r] + redQ[64 + rbase + r];
    float mean = s * (1.f / 256.f);
    float var = fmaf(-mean, mean, q * (1.f / 256.f));
    float rstd = rsqrtf(var + 1e-5f);
    float4 o;
    o.x = (v[r][0] - mean) * rstd * gg.x + ee.x;
    o.y = (v[r][1] - mean) * rstd * gg.y + ee.y;
    o.z = (v[r][2] - mean) * rstd * gg.z + ee.z;
    o.w = (v[r][3] - mean) * rstd * gg.w + ee.w;
    *(float4*)&C[(m0 + rbase + r) * ldc + cb] = o;
  }
}

// ---------------- K0 ----------------
__global__ void __launch_bounds__(256) mqk_kernel(const float* __restrict__ Wq,
                                                  const float* __restrict__ Wk) {
  __shared__ float sWq[16 * 68];
  __shared__ float sWk[128 * 68];
  int h = blockIdx.x, is = blockIdx.y, tid = threadIdx.x;
  {
    int il = tid >> 4, d4 = tid & 15;
    *(float4*)&sWq[il * 68 + d4 * 4] =
        *(const float4*)&Wq[(size_t)(is * 16 + il) * 256 + h * 64 + d4 * 4];
  }
  for (int jc = 0; jc < 2; jc++) {
    __syncthreads();
#pragma unroll
    for (int it = 0; it < 8; it++) {
      int f = tid + it * 256, j = f >> 4, d4 = f & 15;
      *(float4*)&sWk[j * 68 + d4 * 4] =
          *(const float4*)&Wk[(size_t)(jc * 128 + j) * 256 + h * 64 + d4 * 4];
    }
    __syncthreads();
    int j = tid & 127, ih = tid >> 7;
#pragma unroll 1
    for (int il = ih * 8; il < ih * 8 + 8; il++) {
      float acc = 0.f;
#pragma unroll
      for (int d = 0; d < 64; d++) acc = fmaf(sWq[il * 68 + d], sWk[j * 68 + d], acc);
      g_Wcat[(size_t)(is * 16 + il) * 1280 + h * 256 + jc * 128 + j] = acc;
    }
  }
}

__global__ void copy_wres_kernel(const float* __restrict__ Wres) {
  g_Wcat[(size_t)blockIdx.x * 1280 + 1024 + threadIdx.x] =
      Wres[(size_t)blockIdx.x * 256 + threadIdx.x];
}

// ---------- SIMT GEMM, cp.async double-buffered, warp tile 16x128 ----------
// EPI: 0 store, 1 relu(x+bias), 2 LN(x+bias+resid) (requires gridDim.x==1, ldc==256)
template <int EPI>
__global__ void __launch_bounds__(256, 2) gemm_epi(
    const float* __restrict__ A, const float* __restrict__ W, float* __restrict__ C,
    int K, int ldw, int ldc, const float* __restrict__ bias,
    const float* __restrict__ resid, int ldres,
    const float* __restrict__ gamma, const float* __restrict__ beta) {
  extern __shared__ float smd[];
  float* sAT = smd;                 // [2][32*68]
  float* sB = smd + 2 * 32 * 68;    // [2][32*256]
  __shared__ float redS[128], redQ[128];
  int tid = threadIdx.x, lane = tid & 31, wid = tid >> 5;
  int rbase = (wid >> 1) * 16;
  int colslab = wid & 1;
  int cb = colslab * 128 + lane * 4;
  int m0 = blockIdx.y * 64, n0 = blockIdx.x * 256;
  unsigned long long acc[8][4];
#pragma unroll
  for (int i = 0; i < 8; i++)
#pragma unroll
    for (int j = 0; j < 4; j++) acc[i][j] = 0ull;

  uint32_t sBu = (uint32_t)__cvta_generic_to_shared(sB);
  int kt_n = K >> 5;
  float4 aR[2];
#pragma unroll
  for (int it = 0; it < 8; it++) {
    int f = tid + it * 256, kk = f >> 6, c4 = f & 63;
    cpa16(sBu + (kk * 256 + c4 * 4) * 4, &W[(size_t)kk * ldw + n0 + c4 * 4]);
  }
  CP_COMMIT();
#pragma unroll
  for (int it = 0; it < 2; it++) {
    int f = tid + it * 256, r = f >> 3, kq = f & 7;
    aR[it] = *(const float4*)&A[(size_t)(m0 + r) * K + kq * 4];
  }
#pragma unroll
  for (int it = 0; it < 2; it++) {
    int f = tid + it * 256, r = f >> 3, kq = f & 7;
    sAT[(kq * 4 + 0) * 68 + r] = aR[it].x;
    sAT[(kq * 4 + 1) * 68 + r] = aR[it].y;
    sAT[(kq * 4 + 2) * 68 + r] = aR[it].z;
    sAT[(kq * 4 + 3) * 68 + r] = aR[it].w;
  }
  CP_WAIT0();
  __syncthreads();

  for (int kt = 0; kt < kt_n; kt++) {
    int nb = (kt + 1) & 1;
    if (kt + 1 < kt_n) {
#pragma unroll
      for (int it = 0; it < 8; it++) {
        int f = tid + it * 256, kk = f >> 6, c4 = f & 63;
        cpa16(sBu + (nb * 32 * 256 + kk * 256 + c4 * 4) * 4,
              &W[(size_t)((kt + 1) * 32 + kk) * ldw + n0 + c4 * 4]);
      }
      CP_COMMIT();
#pragma unroll
      for (int it = 0; it < 2; it++) {
        int f = tid + it * 256, r = f >> 3, kq = f & 7;
        aR[it] = *(const float4*)&A[(size_t)(m0 + r) * K + (kt + 1) * 32 + kq * 4];
      }
    }
    const float* cA = sAT + (kt & 1) * 32 * 68;
    const float* cB = sB + (kt & 1) * 32 * 256;
#pragma unroll
    for (int kk = 0; kk < 32; kk++) {
      float4 bv = *(const float4*)&cB[kk * 256 + cb];
      unsigned long long bd0 = dup2(bv.x), bd1 = dup2(bv.y);
      unsigned long long bd2 = dup2(bv.z), bd3 = dup2(bv.w);
      const ulonglong2* ap = (const ulonglong2*)&cA[kk * 68 + rbase];
      ulonglong2 p0 = ap[0], p1 = ap[1], p2 = ap[2], p3 = ap[3];
      unsigned long long arr[8] = {p0.x, p0.y, p1.x, p1.y, p2.x, p2.y, p3.x, p3.y};
#pragma unroll
      for (int rp = 0; rp < 8; rp++) {
        FMA2(acc[rp][0], arr[rp], bd0);
        FMA2(acc[rp][1], arr[rp], bd1);
        FMA2(acc[rp][2], arr[rp], bd2);
        FMA2(acc[rp][3], arr[rp], bd3);
      }
    }
    if (kt + 1 < kt_n) {
      float* nA = sAT + nb * 32 * 68;
#pragma unroll
      for (int it = 0; it < 2; it++) {
        int f = tid + it * 256, r = f >> 3, kq = f & 7;
        nA[(kq * 4 + 0) * 68 + r] = aR[it].x;
        nA[(kq * 4 + 1) * 68 + r] = aR[it].y;
        nA[(kq * 4 + 2) * 68 + r] = aR[it].z;
        nA[(kq * 4 + 3) * 68 + r] = aR[it].w;
      }
      CP_WAIT0();
      __syncthreads();
    }
  }
  // ---- epilogue ----
  if (EPI == 2) {
    float v[16][4];
    float4 bv = *(const float4*)&bias[cb];
#pragma unroll
    for (int rp = 0; rp < 8; rp++) {
      float2 c0v = unpk(acc[rp][0]), c1v = unpk(acc[rp][1]);
      float2 c2v = unpk(acc[rp][2]), c3v = unpk(acc[rp][3]);
      float4 r0 = *(const float4*)&resid[(size_t)(m0 + rbase + 2 * rp) * ldres + cb];
      float4 r1 = *(const float4*)&resid[(size_t)(m0 + rbase + 2 * rp + 1) * ldres + cb];
      v[2 * rp][0] = c0v.x + bv.x + r0.x;
      v[2 * rp][1] = c1v.x + bv.y + r0.y;
      v[2 * rp][2] = c2v.x + bv.z + r0.z;
      v[2 * rp][3] = c3v.x + bv.w + r0.w;
      v[2 * rp + 1][0] = c0v.y + bv.x + r1.x;
      v[2 * rp + 1][1] = c1v.y + bv.y + r1.y;
      v[2 * rp + 1][2] = c2v.y + bv.z + r1.z;
      v[2 * rp + 1][3] = c3v.y + bv.w + r1.w;
    }
    ln_epilogue(v, rbase, colslab, cb, redS, redQ, gamma, beta, C, ldc, (size_t)m0);
    return;
  }
  float bb[4];
  if (EPI == 1) {
    float4 bv = *(const float4*)&bias[n0 + cb];
    bb[0] = bv.x; bb[1] = bv.y; bb[2] = bv.z; bb[3] = bv.w;
  }
#pragma unroll
  for (int rp = 0; rp < 8; rp++) {
    float2 c0v = unpk(acc[rp][0]), c1v = unpk(acc[rp][1]);
    float2 c2v = unpk(acc[rp][2]), c3v = unpk(acc[rp][3]);
    float4 o0 = {c0v.x, c1v.x, c2v.x, c3v.x};
    float4 o1 = {c0v.y, c1v.y, c2v.y, c3v.y};
    if (EPI == 1) {
      o0.x = fmaxf(o0.x + bb[0], 0.f); o0.y = fmaxf(o0.y + bb[1], 0.f);
      o0.z = fmaxf(o0.z + bb[2], 0.f); o0.w = fmaxf(o0.w + bb[3], 0.f);
      o1.x = fmaxf(o1.x + bb[0], 0.f); o1.y = fmaxf(o1.y + bb[1], 0.f);
      o1.z = fmaxf(o1.z + bb[2], 0.f); o1.w = fmaxf(o1.w + bb[3], 0.f);
    }
    *(float4*)&C[(size_t)(m0 + rbase + 2 * rp) * ldc + n0 + cb] = o0;
    *(float4*)&C[(size_t)(m0 + rbase + 2 * rp + 1) * ldc + n0 + cb] = o1;
  }
}

// ---------- K3: head-split GEMM + LN epilogue ----------
__global__ void __launch_bounds__(256, 2) gemm_hs(
    const float* __restrict__ Wv, float* __restrict__ C,
    const float* __restrict__ bias, const float* __restrict__ resid, int ldres,
    const float* __restrict__ gamma, const float* __restrict__ beta) {
  extern __shared__ float smd[];
  float* sAT = smd;                     // [2][16*4*68]
  float* sB = smd + 2 * 16 * 4 * 68;    // [2][16*256]
  __shared__ float redS[128], redQ[128];
  int tid = threadIdx.x, lane = tid & 31, wid = tid >> 5;
  int rbase = (wid >> 1) * 16;
  int colslab = wid & 1;
  int cb = colslab * 128 + lane * 4;
  int hl = colslab * 2 + (lane >> 4);
  int m0 = blockIdx.y * 64;
  unsigned long long acc[8][4];
#pragma unroll
  for (int i = 0; i < 8; i++)
#pragma unroll
    for (int j = 0; j < 4; j++) acc[i][j] = 0ull;

  uint32_t sBu = (uint32_t)__cvta_generic_to_shared(sB);
  float4 aR[4];
#pragma unroll
  for (int it = 0; it < 4; it++) {
    int f = tid + it * 256, kk = f >> 6, c4 = f & 63;
    cpa16(sBu + (kk * 256 + c4 * 4) * 4, &Wv[(size_t)kk * 256 + c4 * 4]);
  }
  CP_COMMIT();
#pragma unroll
  for (int it = 0; it < 4; it++) {
    int f = tid + it * 256, r = f >> 4, q = f & 15, h = q >> 2, kq = q & 3;
    aR[it] = *(const float4*)&g_U[(size_t)(m0 + r) * 1024 + h * 256 + kq * 4];
  }
#pragma unroll
  for (int it = 0; it < 4; it++) {
    int f = tid + it * 256, r = f >> 4, q = f & 15, h = q >> 2, kq = q & 3;
    sAT[((kq * 4 + 0) * 4 + h) * 68 + r] = aR[it].x;
    sAT[((kq * 4 + 1) * 4 + h) * 68 + r] = aR[it].y;
    sAT[((kq * 4 + 2) * 4 + h) * 68 + r] = aR[it].z;
    sAT[((kq * 4 + 3) * 4 + h) * 68 + r] = aR[it].w;
  }
  CP_WAIT0();
  __syncthreads();

  for (int kt = 0; kt < 16; kt++) {
    int nb = (kt + 1) & 1;
    if (kt + 1 < 16) {
#pragma unroll
      for (int it = 0; it < 4; it++) {
        int f = tid + it * 256, kk = f >> 6, c4 = f & 63;
        cpa16(sBu + (nb * 16 * 256 + kk * 256 + c4 * 4) * 4,
              &Wv[(size_t)((kt + 1) * 16 + kk) * 256 + c4 * 4]);
      }
      CP_COMMIT();
#pragma unroll
      for (int it = 0; it < 4; it++) {
        int f = tid + it * 256, r = f >> 4, q = f & 15, h = q >> 2, kq = q & 3;
        aR[it] = *(const float4*)&g_U[(size_t)(m0 + r) * 1024 + h * 256 +
                                      (kt + 1) * 16 + kq * 4];
      }
    }
    const float* cA = sAT + (kt & 1) * 16 * 4 * 68;
    const float* cB = sB + (kt & 1) * 16 * 256;
#pragma unroll
    for (int kk = 0; kk < 16; kk++) {
      float4 bv = *(const float4*)&cB[kk * 256 + cb];
      unsigned long long bd0 = dup2(bv.x), bd1 = dup2(bv.y);
      unsigned long long bd2 = dup2(bv.z), bd3 = dup2(bv.w);
      const ulonglong2* ap = (const ulonglong2*)&cA[(kk * 4 + hl) * 68 + rbase];
      ulonglong2 p0 = ap[0], p1 = ap[1], p2 = ap[2], p3 = ap[3];
      unsigned long long arr[8] = {p0.x, p0.y, p1.x, p1.y, p2.x, p2.y, p3.x, p3.y};
#pragma unroll
      for (int rp = 0; rp < 8; rp++) {
        FMA2(acc[rp][0], arr[rp], bd0);
        FMA2(acc[rp][1], arr[rp], bd1);
        FMA2(acc[rp][2], arr[rp], bd2);
        FMA2(acc[rp][3], arr[rp], bd3);
      }
    }
    if (kt + 1 < 16) {
      float* nA = sAT + nb * 16 * 4 * 68;
#pragma unroll
      for (int it = 0; it < 4; it++) {
        int f = tid + it * 256, r = f >> 4, q = f & 15, h = q >> 2, kq = q & 3;
        nA[((kq * 4 + 0) * 4 + h) * 68 + r] = aR[it].x;
        nA[((kq * 4 + 1) * 4 + h) * 68 + r] = aR[it].y;
        nA[((kq * 4 + 2) * 4 + h) * 68 + r] = aR[it].z;
        nA[((kq * 4 + 3) * 4 + h) * 68 + r] = aR[it].w;
      }
      CP_WAIT0();
      __syncthreads();
    }
  }
  // ---- LN epilogue ----
  float v[16][4];
  float4 bv = *(const float4*)&bias[cb];
#pragma unroll
  for (int rp = 0; rp < 8; rp++) {
    float2 c0v = unpk(acc[rp][0]), c1v = unpk(acc[rp][1]);
    float2 c2v = unpk(acc[rp][2]), c3v = unpk(acc[rp][3]);
    float4 r0 = *(const float4*)&resid[(size_t)(m0 + rbase + 2 * rp) * ldres + cb];
    float4 r1 = *(const float4*)&resid[(size_t)(m0 + rbase + 2 * rp + 1) * ldres + cb];
    v[2 * rp][0] = c0v.x + bv.x + r0.x;
    v[2 * rp][1] = c1v.x + bv.y + r0.y;
    v[2 * rp][2] = c2v.x + bv.z + r0.z;
    v[2 * rp][3] = c3v.x + bv.w + r0.w;
    v[2 * rp + 1][0] = c0v.y + bv.x + r1.x;
    v[2 * rp + 1][1] = c1v.y + bv.y + r1.y;
    v[2 * rp + 1][2] = c2v.y + bv.z + r1.z;
    v[2 * rp + 1][3] = c3v.y + bv.w + r1.w;
  }
  ln_epilogue(v, rbase, colslab, cb, redS, redQ, gamma, beta, C, 256, (size_t)m0);
}

// ---------------- K2: attention ----------------
__global__ void __launch_bounds__(256) attn_u_kernel(
    const float* __restrict__ x_ctx, const float* __restrict__ t_ctx,
    const float* __restrict__ freq, const float* __restrict__ phase) {
  __shared__ float kv[32 * 260];
  __shared__ float p2[4 * 8 * 36];
  __shared__ float slog[128];
  __shared__ __align__(16) float sw[128];
  __shared__ float sfr[64], sph[64];
  int b = blockIdx.x, tid = threadIdx.x;
  int l = tid >> 3, sub = tid & 7;

  if (tid < 64) {
    sfr[tid] = freq[tid];
    sph[tid] = phase[tid];
  }
  {
    int h = tid >> 6, r = tid & 63, s2 = r >> 3, c = r & 7;
    int idx4;
    if (c < 4) idx4 = h * 64 + s2 * 4 + c;
    else if (c < 6) idx4 = h * 64 + 32 + s2 * 2 + (c - 4);
    else idx4 = h * 64 + 48 + s2 * 2 + (c - 6);
    float4 v = *(const float4*)&g_PR[(size_t)b * 1280 + (size_t)idx4 * 4];
    *(float4*)&p2[(h * 8 + s2) * 36 + c * 4] = v;
  }
  __syncthreads();

  float acc[4] = {0.f, 0.f, 0.f, 0.f};
  const float* xsrc = x_ctx + ((size_t)b * 32 + l) * 128 + sub * 16;
  float* kvrow = kv + l * 260;

#pragma unroll
  for (int c = 0; c < 4; c++) {
    float4 v = *(const float4*)&xsrc[c * 4];
    *(float4*)&kvrow[SW(sub * 16 + c * 4)] = v;
#pragma unroll
    for (int h = 0; h < 4; h++) {
      float4 p = *(const float4*)&p2[(h * 8 + sub) * 36 + c * 4];
      acc[h] = fmaf(v.x, p.x, acc[h]);
      acc[h] = fmaf(v.y, p.y, acc[h]);
      acc[h] = fmaf(v.z, p.z, acc[h]);
      acc[h] = fmaf(v.w, p.w, acc[h]);
    }
  }
  {
    float t = t_ctx[(size_t)b * 32 + l];
    float lt = log1pf(fmaxf(t, 0.f));
#pragma unroll
    for (int g = 0; g < 2; g++) {
      float4 sv, cv;
      float ss, cc;
      int k0 = sub * 8 + g * 4;
      float z0 = fmaf(lt, sfr[k0 + 0], sph[k0 + 0]);
      float z1 = fmaf(lt, sfr[k0 + 1], sph[k0 + 1]);
      float z2 = fmaf(lt, sfr[k0 + 2], sph[k0 + 2]);
      float z3 = fmaf(lt, sfr[k0 + 3], sph[k0 + 3]);
      fast_sincos(z0, ss, cc); sv.x = ss; cv.x = cc;
      fast_sincos(z1, ss, cc); sv.y = ss; cv.y = cc;
      fast_sincos(z2, ss, cc); sv.z = ss; cv.z = cc;
      fast_sincos(z3, ss, cc); sv.w = ss; cv.w = cc;
      *(float4*)&kvrow[SW(128 + sub * 8 + g * 4)] = sv;
      *(float4*)&kvrow[SW(192 + sub * 8 + g * 4)] = cv;
#pragma unroll
      for (int h = 0; h < 4; h++) {
        float4 ps = *(const float4*)&p2[(h * 8 + sub) * 36 + (4 + g) * 4];
        float4 pc = *(const float4*)&p2[(h * 8 + sub) * 36 + (6 + g) * 4];
        acc[h] = fmaf(sv.x, ps.x, acc[h]);
        acc[h] = fmaf(sv.y, ps.y, acc[h]);
        acc[h] = fmaf(sv.z, ps.z, acc[h]);
        acc[h] = fmaf(sv.w, ps.w, acc[h]);
        acc[h] = fmaf(cv.x, pc.x, acc[h]);
        acc[h] = fmaf(cv.y, pc.y, acc[h]);
        acc[h] = fmaf(cv.z, pc.z, acc[h]);
        acc[h] = fmaf(cv.w, pc.w, acc[h]);
      }
    }
  }
#pragma unroll
  for (int h = 0; h < 4; h++) {
#pragma unroll
    for (int o = 4; o; o >>= 1) acc[h] += __shfl_xor_sync(0xffffffffu, acc[h], o);
  }
  if (sub < 4) slog[sub * 32 + l] = acc[sub] * 0.125f;
  __syncthreads();
  if (tid < 128) {
    int h = tid >> 5, ll = tid & 31;
    float v = slog[tid];
    float m = wmax(v);
    float e = __expf(v - m);
    float s = wsum(e);
    sw[ll * 4 + h] = e / s;
  }
  __syncthreads();
  // u-phase: 64 threads, thread owns dims j0..j0+3 (float4), all 4 heads
  if (tid < 64) {
    int j0 = tid * 4;
    int sj = SW(j0);  // 16B-aligned, contiguous 4 words
    unsigned long long au[4][2];
#pragma unroll
    for (int d = 0; d < 4; d++) { au[d][0] = 0ull; au[d][1] = 0ull; }
#pragma unroll
    for (int ll = 0; ll < 32; ll++) {
      float4 kq = *(const float4*)&kv[ll * 260 + sj];
      ulonglong2 w2 = *(const ulonglong2*)&sw[ll * 4];
      unsigned long long d0 = dup2(kq.x), d1 = dup2(kq.y);
      unsigned long long d2 = dup2(kq.z), d3 = dup2(kq.w);
      FMA2(au[0][0], d0, w2.x); FMA2(au[0][1], d0, w2.y);
      FMA2(au[1][0], d1, w2.x); FMA2(au[1][1], d1, w2.y);
      FMA2(au[2][0], d2, w2.x); FMA2(au[2][1], d2, w2.y);
      FMA2(au[3][0], d3, w2.x); FMA2(au[3][1], d3, w2.y);
    }
    float2 p01[4], p23[4];
#pragma unroll
    for (int d = 0; d < 4; d++) {
      p01[d] = unpk(au[d][0]);
      p23[d] = unpk(au[d][1]);
    }
    size_t o = (size_t)b * 1024 + j0;
    float4 u0 = {p01[0].x, p01[1].x, p01[2].x, p01[3].x};
    float4 u1 = {p01[0].y, p01[1].y, p01[2].y, p01[3].y};
    float4 u2 = {p23[0].x, p23[1].x, p23[2].x, p23[3].x};
    float4 u3 = {p23[0].y, p23[1].y, p23[2].y, p23[3].y};
    *(float4*)&g_U[o] = u0;
    *(float4*)&g_U[o + 256] = u1;
    *(float4*)&g_U[o + 512] = u2;
    *(float4*)&g_U[o + 768] = u3;
  }
}

// ---------------- launch ----------------
extern "C" void kernel_launch(void* const* d_in, const int* in_sizes, int n_in,
                              void* d_out, int out_size) {
  const float* x_u   = (const float*)d_in[0];
  const float* x_ctx = (const float*)d_in[1];
  const float* t_ctx = (const float*)d_in[2];
  const float* freq  = (const float*)d_in[3];
  const float* phase = (const float*)d_in[4];
  const float* Wq    = (const float*)d_in[5];
  const float* Wk    = (const float*)d_in[6];
  const float* Wv    = (const float*)d_in[7];
  const float* Wres  = (const float*)d_in[8];
  const float* bres  = (const float*)d_in[9];
  const float* W1    = (const float*)d_in[10];
  const float* b1    = (const float*)d_in[11];
  const float* W2    = (const float*)d_in[12];
  const float* b2    = (const float*)d_in[13];
  const float* g1    = (const float*)d_in[14];
  const float* be1   = (const float*)d_in[15];
  const float* g2    = (const float*)d_in[16];
  const float* be2   = (const float*)d_in[17];
  float* out = (float*)d_out;

  float *pWcat, *pPR, *pZ1, *pH1;
  cudaGetSymbolAddress((void**)&pWcat, g_Wcat);
  cudaGetSymbolAddress((void**)&pPR, g_PR);
  cudaGetSymbolAddress((void**)&pZ1, g_Z1);
  cudaGetSymbolAddress((void**)&pH1, g_H1);

  int smemEpi = (2 * 32 * 68 + 2 * 32 * 256) * 4;     // 82,944 B
  int smemHs = (2 * 16 * 4 * 68 + 2 * 16 * 256) * 4;  // 67,584 B
  cudaFuncSetAttribute(gemm_epi<0>, cudaFuncAttributeMaxDynamicSharedMemorySize, smemEpi);
  cudaFuncSetAttribute(gemm_epi<1>, cudaFuncAttributeMaxDynamicSharedMemorySize, smemEpi);
  cudaFuncSetAttribute(gemm_epi<2>, cudaFuncAttributeMaxDynamicSharedMemorySize, smemEpi);
  cudaFuncSetAttribute(gemm_hs, cudaFuncAttributeMaxDynamicSharedMemorySize, smemHs);

  mqk_kernel<<<dim3(4, 8), 256>>>(Wq, Wk);
  copy_wres_kernel<<<128, 256>>>(Wres);

  // K1: P|R = x_u @ Wcat
  gemm_epi<0><<<dim3(5, 256), 256, smemEpi>>>(x_u, pWcat, pPR, 128, 1280, 1280,
                                              nullptr, nullptr, 0, nullptr, nullptr);

  // K2: attention -> u
  attn_u_kernel<<<BB, 256>>>(x_ctx, t_ctx, freq, phase);

  // K3: z1 = LN(u_h @ Wv_h + R + bres)   (fused LN epilogue)
  gemm_hs<<<dim3(1, 256), 256, smemHs>>>(Wv, pZ1, bres, pPR + 1024, 1280, g1, be1);

  // K4: h1 = relu(z1 @ W1 + b1)
  gemm_epi<1><<<dim3(1, 256), 256, smemEpi>>>(pZ1, W1, pH1, 256, 256, 256,
                                              b1, nullptr, 0, nullptr, nullptr);

  // K5: out = LN(h1 @ W2 + b2 + z1)   (fused LN epilogue)
  gemm_epi<2><<<dim3(1, 256), 256, smemEpi>>>(pH1, W2, out, 256, 256, 256,
                                              b2, pZ1, 256, g2, be2);
}